// round 11
// baseline (speedup 1.0000x reference)
#include <cuda_runtime.h>
#include <cuda_fp16.h>
#include <math.h>
#include <stdint.h>

#define BB     4
#define SS     2048
#define DD     1024
#define NIN    8192
#define NPROC  4096
#define DR     256
#define HH     512
#define KIN    4096
#define KPROC  2048

#define SCALE_B   4096.0f
#define INV_SCALE 2.44140625e-4f

// ---------------- scratch (static device memory; no allocs) ----------------
__device__ float g_gc[BB * DD];
__device__ float g_logits[BB * NIN];
__device__ int   g_iidx[BB * KIN];
__device__ int   g_iidx2[BB * KIN];
__device__ int   g_pidx[BB * KPROC];
__device__ int   g_pidx2[BB * KPROC];
__device__ float g_scores[BB * NPROC];

__align__(16) __device__ __half g_xh[(size_t)BB * SS * DD];
__align__(16) __device__ __half g_xl[(size_t)BB * SS * DD];
__align__(16) __device__ __half g_iph[(size_t)NIN * DD];
__align__(16) __device__ __half g_ipl[(size_t)NIN * DD];
__align__(16) __device__ __half g_selh[(size_t)BB * SS * KIN];
__align__(16) __device__ __half g_sell[(size_t)BB * SS * KIN];
__align__(16) __device__ __half g_wgh[(size_t)BB * NPROC * KIN];
__align__(16) __device__ __half g_wgl[(size_t)BB * NPROC * KIN];
__align__(16) __device__ __half g_sph[(size_t)BB * SS * KPROC];
__align__(16) __device__ __half g_poth[(size_t)BB * DD * KPROC];
__align__(16) __device__ __half g_proch[(size_t)BB * SS * NPROC];   // fp16 proc

__device__ __forceinline__ float gelu_f(float x) {
    return 0.5f * x * (1.0f + erff(x * 0.70710678118654752440f));
}
__device__ __forceinline__ void split16(float v, __half& h, __half& l) {
    h = __float2half_rn(v);
    l = __float2half_rn(v - __half2float(h));
}

__device__ __forceinline__ uint32_t s2u(const void* p) {
    uint32_t a;
    asm("{ .reg .u64 t; cvta.to.shared.u64 t, %1; cvt.u32.u64 %0, t; }" : "=r"(a) : "l"(p));
    return a;
}
__device__ __forceinline__ void cpa16h(uint32_t dst, const __half* src) {
    asm volatile("cp.async.cg.shared.global [%0], [%1], 16;" :: "r"(dst), "l"(src));
}
__device__ __forceinline__ void cpacommit() { asm volatile("cp.async.commit_group;" ::: "memory"); }
__device__ __forceinline__ void cpawait2()  { asm volatile("cp.async.wait_group 2;" ::: "memory"); }

__device__ __forceinline__ void ldsm4(uint32_t* r, uint32_t a) {
    asm volatile("ldmatrix.sync.aligned.m8n8.x4.shared.b16 {%0,%1,%2,%3}, [%4];"
        : "=r"(r[0]), "=r"(r[1]), "=r"(r[2]), "=r"(r[3]) : "r"(a));
}
__device__ __forceinline__ void mma16f(float* c, const uint32_t* a, const uint32_t* b) {
    asm volatile("mma.sync.aligned.m16n8k16.row.col.f32.f16.f16.f32 "
        "{%0,%1,%2,%3}, {%4,%5,%6,%7}, {%8,%9}, {%0,%1,%2,%3};"
        : "+f"(c[0]), "+f"(c[1]), "+f"(c[2]), "+f"(c[3])
        : "r"(a[0]), "r"(a[1]), "r"(a[2]), "r"(a[3]), "r"(b[0]), "r"(b[1]));
}
__device__ __forceinline__ void mma16h(uint32_t* c, const uint32_t* a, const uint32_t* b) {
    asm volatile("mma.sync.aligned.m16n8k16.row.col.f16.f16.f16.f16 "
        "{%0,%1}, {%2,%3,%4,%5}, {%6,%7}, {%0,%1};"
        : "+r"(c[0]), "+r"(c[1])
        : "r"(a[0]), "r"(a[1]), "r"(a[2]), "r"(a[3]), "r"(b[0]), "r"(b[1]));
}

// ===== fp16 split GEMM: C[128m x 128n], 512 threads, 16 warps (4x4), 32x32/warp =====
// PASSES=3: AhBh(f32acc) + (AhBl + AlBh)(f16acc). PASSES=1: AhBh only.
// OUTMODE: 0 = fp32, 1 = fp16 hi/lo split planes, 2 = fp16 single plane.
// FUSEGW: blocks with blockIdx.x >= NXG run the PW gather/split instead.
#define SPAD   80
#define PLANE  10240               // 128 rows * 80B
#define NXG    32                  // GEMM n-extent in blocks

template <int PASSES, int ACT, int OUTMODE, int GATHB, int FUSEGW>
__global__ void __launch_bounds__(512, 1)
k_gemm_h(const __half* __restrict__ Ah, const __half* __restrict__ Al,
         const __half* __restrict__ Bh, const __half* __restrict__ Bl,
         const int* __restrict__ bIdx, int idxB,
         const float* __restrict__ PW,
         void* __restrict__ C0v, void* __restrict__ C1v,
         int K, int ldc, size_t aB, size_t bB, size_t cB) {
    extern __shared__ char smem[];
    const int tid = threadIdx.x, bz = blockIdx.z;

    if (FUSEGW && blockIdx.x >= NXG) {
        // ---- gatherW: Wg[b][p][k] = split(PW[p][iidx2[b][k]] * SCALE_B) ----
        int gx = blockIdx.x - NXG;                 // 0..7
        int p0 = (blockIdx.y * 8 + gx) * 32;       // 16*8*32 = 4096 rows
        int* si = (int*)smem;
        for (int k0 = 0; k0 < KIN; k0 += 512) {
            si[tid] = bIdx[(size_t)bz * KIN + k0 + tid];
            __syncthreads();
            int col = si[tid];
#pragma unroll 4
            for (int pp = 0; pp < 32; pp++) {
                int p = p0 + pp;
                float v = PW[(size_t)p * NIN + col] * SCALE_B;
                __half h, l;
                split16(v, h, l);
                size_t o = ((size_t)bz * NPROC + p) * KIN + k0 + tid;
                g_wgh[o] = h;
                g_wgl[o] = l;
            }
            __syncthreads();
        }
        return;
    }

    constexpr uint32_t OFFB = (PASSES == 3 ? 2u : 1u) * PLANE;
    constexpr uint32_t STG  = (PASSES == 3 ? 4u : 2u) * PLANE;

    const int m0 = blockIdx.y * 128, n0 = blockIdx.x * 128;
    Ah += bz * aB + (size_t)m0 * K;
    if (PASSES == 3) Al += bz * aB + (size_t)m0 * K;
    const uint32_t s0 = s2u(smem);

    const int lr = tid >> 2, lg = tid & 3;
    const size_t go = (size_t)lr * K + lg * 8;
    size_t bgo;
    if (GATHB) {
        int r0 = bIdx[(size_t)bz * idxB + n0 + lr];
        bgo = (size_t)r0 * K + lg * 8;
    } else {
        Bh += bz * bB + (size_t)n0 * K;
        if (PASSES == 3) Bl += bz * bB + (size_t)n0 * K;
        bgo = go;
    }
    const uint32_t so = (uint32_t)(lr * SPAD + lg * 16);

    const int lane = tid & 31, wid = tid >> 5;
    const int wm = (wid & 3) * 32, wn = (wid >> 2) * 32;
    const int l8 = lane & 7, mid = lane >> 3;
    uint32_t aoff[2][2], boff[2][2];
#pragma unroll
    for (int mt = 0; mt < 2; mt++)
#pragma unroll
        for (int ks = 0; ks < 2; ks++)
            aoff[mt][ks] = (uint32_t)((wm + mt * 16 + (mid & 1) * 8 + l8) * SPAD
                                      + ((mid >> 1) * 8 + ks * 16) * 2);
#pragma unroll
    for (int p = 0; p < 2; p++)
#pragma unroll
        for (int ks = 0; ks < 2; ks++)
            boff[p][ks] = (uint32_t)(OFFB + (wn + p * 16 + (mid >> 1) * 8 + l8) * SPAD
                                     + ((mid & 1) * 8 + ks * 16) * 2);

    float acc[2][4][4];
    uint32_t acx[2][4][2];
#pragma unroll
    for (int mt = 0; mt < 2; mt++)
#pragma unroll
        for (int nt = 0; nt < 4; nt++) {
#pragma unroll
            for (int e = 0; e < 4; e++) acc[mt][nt][e] = 0.f;
            acx[mt][nt][0] = 0u; acx[mt][nt][1] = 0u;
        }

    const int nc = K >> 5;

#define LOADSTG(c) do { \
    uint32_t sb_ = s0 + ((c) & 3) * STG; \
    size_t ko_ = (size_t)(c) * 32; \
    cpa16h(sb_ + so,        Ah + go + ko_); \
    cpa16h(sb_ + OFFB + so, Bh + bgo + ko_); \
    if (PASSES == 3) { \
        cpa16h(sb_ + PLANE + so,        Al + go + ko_); \
        cpa16h(sb_ + OFFB + PLANE + so, Bl + bgo + ko_); \
    } \
    cpacommit(); \
} while (0)

    LOADSTG(0); LOADSTG(1); LOADSTG(2);

    for (int c = 0; c < nc; c++) {
        cpawait2();
        __syncthreads();
        if (c + 3 < nc) LOADSTG(c + 3); else cpacommit();
        const uint32_t sb = s0 + (c & 3) * STG;
#pragma unroll
        for (int ks = 0; ks < 2; ks++) {
            uint32_t fa[2][4], fb[2][4];
#pragma unroll
            for (int mt = 0; mt < 2; mt++) ldsm4(fa[mt], sb + aoff[mt][ks]);
#pragma unroll
            for (int p = 0; p < 2; p++) ldsm4(fb[p], sb + boff[p][ks]);
#pragma unroll
            for (int mt = 0; mt < 2; mt++)
#pragma unroll
                for (int nt = 0; nt < 4; nt++)
                    mma16f(acc[mt][nt], fa[mt], &fb[nt >> 1][(nt & 1) * 2]);
            if (PASSES == 3) {
                uint32_t fal[2][4], fbl[2][4];
#pragma unroll
                for (int p = 0; p < 2; p++) ldsm4(fbl[p], sb + boff[p][ks] + PLANE);
#pragma unroll
                for (int mt = 0; mt < 2; mt++)
#pragma unroll
                    for (int nt = 0; nt < 4; nt++)
                        mma16h(acx[mt][nt], fa[mt], &fbl[nt >> 1][(nt & 1) * 2]);
#pragma unroll
                for (int mt = 0; mt < 2; mt++) ldsm4(fal[mt], sb + aoff[mt][ks] + PLANE);
#pragma unroll
                for (int mt = 0; mt < 2; mt++)
#pragma unroll
                    for (int nt = 0; nt < 4; nt++)
                        mma16h(acx[mt][nt], fal[mt], &fb[nt >> 1][(nt & 1) * 2]);
            }
        }
    }
#undef LOADSTG

    const int qr = lane >> 2, qk = lane & 3;
#pragma unroll
    for (int mt = 0; mt < 2; mt++) {
#pragma unroll
        for (int nt = 0; nt < 4; nt++) {
            const int r = m0 + wm + mt * 16 + qr;
            const int cc = n0 + wn + nt * 8 + qk * 2;
            float v0, v1, v2, v3;
            if (PASSES == 3) {
                float2 x01 = __half22float2(*(__half2*)&acx[mt][nt][0]);
                float2 x23 = __half22float2(*(__half2*)&acx[mt][nt][1]);
                v0 = (acc[mt][nt][0] + x01.x) * INV_SCALE;
                v1 = (acc[mt][nt][1] + x01.y) * INV_SCALE;
                v2 = (acc[mt][nt][2] + x23.x) * INV_SCALE;
                v3 = (acc[mt][nt][3] + x23.y) * INV_SCALE;
            } else {
                v0 = acc[mt][nt][0] * INV_SCALE;
                v1 = acc[mt][nt][1] * INV_SCALE;
                v2 = acc[mt][nt][2] * INV_SCALE;
                v3 = acc[mt][nt][3] * INV_SCALE;
            }
            if (ACT) { v0 = gelu_f(v0); v1 = gelu_f(v1); v2 = gelu_f(v2); v3 = gelu_f(v3); }
            if (OUTMODE == 1) {
                __half* C0 = (__half*)C0v + bz * cB;
                __half* C1 = (__half*)C1v + bz * cB;
                __half h0, l0, h1, l1;
                split16(v0, h0, l0); split16(v1, h1, l1);
                *(__half2*)&C0[(size_t)r * ldc + cc] = __halves2half2(h0, h1);
                *(__half2*)&C1[(size_t)r * ldc + cc] = __halves2half2(l0, l1);
                split16(v2, h0, l0); split16(v3, h1, l1);
                *(__half2*)&C0[(size_t)(r + 8) * ldc + cc] = __halves2half2(h0, h1);
                *(__half2*)&C1[(size_t)(r + 8) * ldc + cc] = __halves2half2(l0, l1);
            } else if (OUTMODE == 2) {
                __half* C0 = (__half*)C0v + bz * cB;
                *(__half2*)&C0[(size_t)r * ldc + cc] =
                    __halves2half2(__float2half_rn(v0), __float2half_rn(v1));
                *(__half2*)&C0[(size_t)(r + 8) * ldc + cc] =
                    __halves2half2(__float2half_rn(v2), __float2half_rn(v3));
            } else {
                float* C0 = (float*)C0v + bz * cB;
                float2 w0 = {v0, v1}, w1 = {v2, v3};
                *(float2*)&C0[(size_t)r * ldc + cc] = w0;
                *(float2*)&C0[(size_t)(r + 8) * ldc + cc] = w1;
            }
        }
    }
}

// ---------------- launch 0: gcmax + split(x) + split(IP) fused ----------------
__global__ void k_prep0(const float* __restrict__ x, const float* __restrict__ IP) {
    int bx = blockIdx.x;
    if (bx < 16) {
        int b = bx >> 2, d = (bx & 3) * 256 + threadIdx.x;
        const float* p = x + (size_t)b * SS * DD + d;
        __half* ph = g_xh + (size_t)b * SS * DD + d;
        __half* pl = g_xl + (size_t)b * SS * DD + d;
        float m = -3.4e38f;
        for (int s = 0; s < SS; s++) {
            float v = p[(size_t)s * DD];
            m = fmaxf(m, v);
            __half h, l;
            split16(v, h, l);
            ph[(size_t)s * DD] = h;
            pl[(size_t)s * DD] = l;
        }
        g_gc[b * DD + d] = m;
    } else {
        size_t i = (size_t)(bx - 16) * 256 + threadIdx.x;
        float4 v = ((const float4*)IP)[i];
        __half hx, lx, hy, ly, hz, lz, hw, lw;
        split16(v.x * SCALE_B, hx, lx); split16(v.y * SCALE_B, hy, ly);
        split16(v.z * SCALE_B, hz, lz); split16(v.w * SCALE_B, hw, lw);
        ((__half2*)g_iph)[2 * i]     = __halves2half2(hx, hy);
        ((__half2*)g_iph)[2 * i + 1] = __halves2half2(hz, hw);
        ((__half2*)g_ipl)[2 * i]     = __halves2half2(lx, ly);
        ((__half2*)g_ipl)[2 * i + 1] = __halves2half2(lz, lw);
    }
}

// ---------------- launch 1: full router MLP + logits slice ----------------
__global__ void k_mlp_logits(const float* __restrict__ W1, const float* __restrict__ b1,
                             const float* __restrict__ lng, const float* __restrict__ lnb,
                             const float* __restrict__ W2, const float* __restrict__ b2,
                             const float* __restrict__ NK) {
    const int b = blockIdx.y;
    const int nb0 = blockIdx.x * (NIN / 16);
    __shared__ float sin[DD];
    __shared__ float sh[HH];
    __shared__ float sq[DR];
    __shared__ float red[8];
    __shared__ float smu, svar;
    const int tid = threadIdx.x, wid = tid >> 5, lane = tid & 31;

    for (int d = tid; d < DD; d += 256) sin[d] = g_gc[b * DD + d];
    __syncthreads();

    for (int o = wid; o < HH; o += 8) {
        float s = 0.f;
        for (int d = lane; d < DD; d += 32) s = fmaf(W1[(size_t)o * DD + d], sin[d], s);
#pragma unroll
        for (int off = 16; off; off >>= 1) s += __shfl_xor_sync(0xffffffffu, s, off);
        if (lane == 0) sh[o] = gelu_f(s + b1[o]);
    }
    __syncthreads();

    float v0 = sh[tid], v1 = sh[tid + 256];
    float s = v0 + v1;
#pragma unroll
    for (int off = 16; off; off >>= 1) s += __shfl_xor_sync(0xffffffffu, s, off);
    if (lane == 0) red[wid] = s;
    __syncthreads();
    if (tid == 0) { float t = 0.f; for (int w = 0; w < 8; w++) t += red[w]; smu = t / HH; }
    __syncthreads();
    float mu = smu;
    float d0 = v0 - mu, d1 = v1 - mu;
    float s2 = d0 * d0 + d1 * d1;
#pragma unroll
    for (int off = 16; off; off >>= 1) s2 += __shfl_xor_sync(0xffffffffu, s2, off);
    __syncthreads();
    if (lane == 0) red[wid] = s2;
    __syncthreads();
    if (tid == 0) { float t = 0.f; for (int w = 0; w < 8; w++) t += red[w]; svar = t / HH; }
    __syncthreads();
    float rstd = rsqrtf(svar + 1e-5f);
    sh[tid]       = d0 * rstd * lng[tid] + lnb[tid];
    sh[tid + 256] = d1 * rstd * lng[tid + 256] + lnb[tid + 256];
    __syncthreads();

    for (int o = wid; o < DR; o += 8) {
        float q = 0.f;
        for (int d = lane; d < HH; d += 32) q = fmaf(W2[(size_t)o * HH + d], sh[d], q);
#pragma unroll
        for (int off = 16; off; off >>= 1) q += __shfl_xor_sync(0xffffffffu, q, off);
        if (lane == 0) sq[o] = q + b2[o];
    }
    __syncthreads();

    for (int o = wid; o < NIN / 16; o += 8) {
        int oo = nb0 + o;
        float lg = 0.f;
        for (int d = lane; d < DR; d += 32) lg = fmaf(NK[(size_t)oo * DR + d], sq[d], lg);
#pragma unroll
        for (int off = 16; off; off >>= 1) lg += __shfl_xor_sync(0xffffffffu, lg, off);
        if (lane == 0) g_logits[(size_t)b * NIN + oo] = lg * 0.0625f;
    }
}

// ---------------- exact top-k set selection via counting rank ----------------
__global__ void k_select(const float* __restrict__ vals, int n, int k, int* __restrict__ idx) {
    int b = blockIdx.y;
    const float* v = vals + (size_t)b * n;
    int i = blockIdx.x * 256 + threadIdx.x;
    float vi = v[i];
    __shared__ float sv[256];
    int r = 0;
    for (int t0 = 0; t0 < n; t0 += 256) {
        sv[threadIdx.x] = v[t0 + threadIdx.x];
        __syncthreads();
#pragma unroll 8
        for (int t = 0; t < 256; t++) {
            float vj = sv[t];
            int j = t0 + t;
            r += (vj > vi) || (vj == vi && j < i);
        }
        __syncthreads();
    }
    if (r < k) idx[(size_t)b * k + r] = i;
}

// ---------------- sort selected index list ascending ----------------
__global__ void k_order(const int* __restrict__ in, int* __restrict__ outp, int k) {
    int b = blockIdx.y;
    const int* v = in + (size_t)b * k;
    int i = blockIdx.x * 256 + threadIdx.x;
    int vi = v[i];
    __shared__ int sv[256];
    int cnt = 0;
    for (int t0 = 0; t0 < k; t0 += 256) {
        sv[threadIdx.x] = v[t0 + threadIdx.x];
        __syncthreads();
#pragma unroll 8
        for (int t = 0; t < 256; t++) cnt += (sv[t] < vi);
        __syncthreads();
    }
    outp[(size_t)b * k + cnt] = vi;
}

// ---------------- scores[b][p] = mean_s proc[b][s][p] (fp16 proc) ----------------
__global__ void k_scores() {
    int b = blockIdx.y;
    int p = blockIdx.x * 256 + threadIdx.x;
    const __half* base = g_proch + (size_t)b * SS * NPROC + p;
    float s = 0.f;
    for (int t = 0; t < SS; t++) s += __half2float(base[(size_t)t * NPROC]);
    g_scores[b * NPROC + p] = s * (1.0f / SS);
}

// ---------------- fused: gathersp (65536 blocks) + po_t (8192 blocks) ----------
__global__ void k_gsp_pot(const float* __restrict__ PO) {
    int bid = blockIdx.x;
    if (bid < 65536) {
        int kx = (bid & 7) * 256 + threadIdx.x;
        int s = (bid >> 3) & 2047;
        int b = bid >> 14;
        int pi = g_pidx2[(size_t)b * KPROC + kx];
        g_sph[((size_t)b * SS + s) * KPROC + kx] =
            g_proch[((size_t)b * SS + s) * NPROC + pi];
    } else {
        __shared__ float t[32][33];
        int id = bid - 65536;
        int k0 = (id & 63) * 32;
        int d0 = ((id >> 6) & 31) * 32;
        int b = id >> 11;
        int tx = threadIdx.x & 31, ty = threadIdx.x >> 5;
        for (int i = ty; i < 32; i += 8) {
            int pi = g_pidx2[(size_t)b * KPROC + k0 + i];
            t[i][tx] = PO[(size_t)pi * DD + d0 + tx];
        }
        __syncthreads();
        for (int i = ty; i < 32; i += 8)
            g_poth[((size_t)b * DD + d0 + i) * KPROC + k0 + tx] =
                __float2half_rn(t[tx][i] * SCALE_B);
    }
}

// ---------------- host side ----------------
extern "C" void kernel_launch(void* const* d_in, const int* in_sizes, int n_in,
                              void* d_out, int out_size) {
    const float* x   = (const float*)d_in[0];
    const float* W1  = (const float*)d_in[1];
    const float* b1  = (const float*)d_in[2];
    const float* lng = (const float*)d_in[3];
    const float* lnb = (const float*)d_in[4];
    const float* W2  = (const float*)d_in[5];
    const float* b2  = (const float*)d_in[6];
    const float* NK  = (const float*)d_in[7];
    const float* IP  = (const float*)d_in[8];
    const float* PW  = (const float*)d_in[9];
    const float* PO  = (const float*)d_in[10];
    float* out = (float*)d_out;

    void *p_logits, *p_iidx, *p_iidx2, *p_pidx, *p_pidx2, *p_scores;
    void *p_xh, *p_xl, *p_iph, *p_ipl, *p_selh, *p_sell, *p_wgh, *p_wgl;
    void *p_proch, *p_sph, *p_poth;
    cudaGetSymbolAddress(&p_logits, g_logits);
    cudaGetSymbolAddress(&p_iidx, g_iidx);
    cudaGetSymbolAddress(&p_iidx2, g_iidx2);
    cudaGetSymbolAddress(&p_pidx, g_pidx);
    cudaGetSymbolAddress(&p_pidx2, g_pidx2);
    cudaGetSymbolAddress(&p_scores, g_scores);
    cudaGetSymbolAddress(&p_xh, g_xh);
    cudaGetSymbolAddress(&p_xl, g_xl);
    cudaGetSymbolAddress(&p_iph, g_iph);
    cudaGetSymbolAddress(&p_ipl, g_ipl);
    cudaGetSymbolAddress(&p_selh, g_selh);
    cudaGetSymbolAddress(&p_sell, g_sell);
    cudaGetSymbolAddress(&p_wgh, g_wgh);
    cudaGetSymbolAddress(&p_wgl, g_wgl);
    cudaGetSymbolAddress(&p_proch, g_proch);
    cudaGetSymbolAddress(&p_sph, g_sph);
    cudaGetSymbolAddress(&p_poth, g_poth);

    const int SM3 = 4 * 4 * PLANE;   // 163840
    const int SM1 = 4 * 2 * PLANE;   //  81920
    cudaFuncSetAttribute((const void*)&k_gemm_h<3, 1, 1, 1, 1>, cudaFuncAttributeMaxDynamicSharedMemorySize, SM3);
    cudaFuncSetAttribute((const void*)&k_gemm_h<3, 1, 2, 0, 0>, cudaFuncAttributeMaxDynamicSharedMemorySize, SM3);
    cudaFuncSetAttribute((const void*)&k_gemm_h<1, 0, 0, 0, 0>, cudaFuncAttributeMaxDynamicSharedMemorySize, SM1);

    // 0) prep: gcmax + split(x) + split(IP)
    k_prep0<<<16 + (NIN * DD / 4) / 256, 256>>>(x, IP);

    // 1) router MLP + logits
    k_mlp_logits<<<dim3(16, BB), 256>>>(W1, b1, lng, lnb, W2, b2, NK);

    // 2) input selection (top-4096 of 8192)
    k_select<<<dim3(NIN / 256, BB), 256>>>((const float*)p_logits, NIN, KIN, (int*)p_iidx);

    // 3) sort index list ascending
    k_order<<<dim3(KIN / 256, BB), 256>>>((const int*)p_iidx, (int*)p_iidx2, KIN);

    // 4) sel GEMM + fused gatherW (blocks x >= 32 gather PW columns concurrently)
    k_gemm_h<3, 1, 1, 1, 1><<<dim3(NXG + 8, 16, BB), 512, SM3>>>(
        (const __half*)p_xh, (const __half*)p_xl, (const __half*)p_iph, (const __half*)p_ipl,
        (const int*)p_iidx2, KIN, PW, p_selh, p_sell, DD, KIN,
        (size_t)SS * DD, 0, (size_t)SS * KIN);

    // 5) proc GEMM -> fp16 proc
    k_gemm_h<3, 1, 2, 0, 0><<<dim3(NPROC / 128, SS / 128, BB), 512, SM3>>>(
        (const __half*)p_selh, (const __half*)p_sell, (const __half*)p_wgh, (const __half*)p_wgl,
        nullptr, 0, nullptr, p_proch, nullptr, KIN, NPROC,
        (size_t)SS * KIN, (size_t)NPROC * KIN, (size_t)SS * NPROC);

    // 6-8) process selection (sorted)
    k_scores<<<dim3(NPROC / 256, BB), 256>>>();
    k_select<<<dim3(NPROC / 256, BB), 256>>>((const float*)p_scores, NPROC, KPROC, (int*)p_pidx);
    k_order<<<dim3(KPROC / 256, BB), 256>>>((const int*)p_pidx, (int*)p_pidx2, KPROC);

    // 9) fused gathersp + po_t
    k_gsp_pot<<<65536 + 8192, 256>>>(PO);

    // 10) out GEMM, 1-pass fp16
    k_gemm_h<1, 0, 0, 0, 0><<<dim3(DD / 128, SS / 128, BB), 512, SM1>>>(
        (const __half*)p_sph, (const __half*)p_sph, (const __half*)p_poth, (const __half*)p_poth,
        nullptr, 0, nullptr, out, nullptr, KPROC, DD,
        (size_t)SS * KPROC, (size_t)DD * KPROC, (size_t)SS * DD);
}

// round 13
// speedup vs baseline: 1.0110x; 1.0110x over previous
#include <cuda_runtime.h>
#include <cuda_fp16.h>
#include <math.h>
#include <stdint.h>

#define BB     4
#define SS     2048
#define DD     1024
#define NIN    8192
#define NPROC  4096
#define DR     256
#define HH     512
#define KIN    4096
#define KPROC  2048

#define SCALE_B   4096.0f
#define INV_SCALE 2.44140625e-4f

// ---------------- scratch (static device memory; no allocs) ----------------
__device__ float g_gc[BB * DD];
__device__ float g_logits[BB * NIN];
__device__ int   g_iidx[BB * KIN];
__device__ int   g_iidx2[BB * KIN];
__device__ int   g_pidx[BB * KPROC];
__device__ int   g_pidx2[BB * KPROC];
__device__ float g_scores[BB * NPROC];

__align__(16) __device__ __half g_xh[(size_t)BB * SS * DD];
__align__(16) __device__ __half g_xl[(size_t)BB * SS * DD];
__align__(16) __device__ __half g_iph[(size_t)NIN * DD];
__align__(16) __device__ __half g_ipl[(size_t)NIN * DD];
__align__(16) __device__ __half g_selh[(size_t)BB * SS * KIN];
__align__(16) __device__ __half g_sell[(size_t)BB * SS * KIN];
__align__(16) __device__ __half g_wgh[(size_t)BB * NPROC * KIN];
__align__(16) __device__ __half g_wgl[(size_t)BB * NPROC * KIN];
__align__(16) __device__ __half g_sph[(size_t)BB * SS * KPROC];
__align__(16) __device__ __half g_poth[(size_t)BB * DD * KPROC];
__align__(16) __device__ __half g_proch[(size_t)BB * SS * NPROC];

__device__ __forceinline__ float gelu_f(float x) {
    return 0.5f * x * (1.0f + erff(x * 0.70710678118654752440f));
}
__device__ __forceinline__ void split16(float v, __half& h, __half& l) {
    h = __float2half_rn(v);
    l = __float2half_rn(v - __half2float(h));
}

__device__ __forceinline__ uint32_t s2u(const void* p) {
    uint32_t a;
    asm("{ .reg .u64 t; cvta.to.shared.u64 t, %1; cvt.u32.u64 %0, t; }" : "=r"(a) : "l"(p));
    return a;
}
__device__ __forceinline__ void cpa16h(uint32_t dst, const __half* src) {
    asm volatile("cp.async.cg.shared.global [%0], [%1], 16;" :: "r"(dst), "l"(src));
}
__device__ __forceinline__ void cpacommit() { asm volatile("cp.async.commit_group;" ::: "memory"); }
__device__ __forceinline__ void cpawait2()  { asm volatile("cp.async.wait_group 2;" ::: "memory"); }

__device__ __forceinline__ void ldsm4(uint32_t* r, uint32_t a) {
    asm volatile("ldmatrix.sync.aligned.m8n8.x4.shared.b16 {%0,%1,%2,%3}, [%4];"
        : "=r"(r[0]), "=r"(r[1]), "=r"(r[2]), "=r"(r[3]) : "r"(a));
}
__device__ __forceinline__ void mma16f(float* c, const uint32_t* a, const uint32_t* b) {
    asm volatile("mma.sync.aligned.m16n8k16.row.col.f32.f16.f16.f32 "
        "{%0,%1,%2,%3}, {%4,%5,%6,%7}, {%8,%9}, {%0,%1,%2,%3};"
        : "+f"(c[0]), "+f"(c[1]), "+f"(c[2]), "+f"(c[3])
        : "r"(a[0]), "r"(a[1]), "r"(a[2]), "r"(a[3]), "r"(b[0]), "r"(b[1]));
}
__device__ __forceinline__ void mma16h(uint32_t* c, const uint32_t* a, const uint32_t* b) {
    asm volatile("mma.sync.aligned.m16n8k16.row.col.f16.f16.f16.f16 "
        "{%0,%1}, {%2,%3,%4,%5}, {%6,%7}, {%0,%1};"
        : "+r"(c[0]), "+r"(c[1])
        : "r"(a[0]), "r"(a[1]), "r"(a[2]), "r"(a[3]), "r"(b[0]), "r"(b[1]));
}

// ===== fp16 split GEMM: C[128m x 128n], 512 threads, 16 warps (4x4), 32x32/warp =====
// PASSES=3: AhBh(f32acc) + (AhBl + AlBh)(f16acc). PASSES=1: AhBh only.
// OUTMODE: 0 = fp32, 1 = fp16 hi/lo split planes, 2 = fp16 single plane.
#define SPAD   80
#define PLANE  10240               // 128 rows * 80B

template <int PASSES, int ACT, int OUTMODE, int GATHB>
__global__ void __launch_bounds__(512, 1)
k_gemm_h(const __half* __restrict__ Ah, const __half* __restrict__ Al,
         const __half* __restrict__ Bh, const __half* __restrict__ Bl,
         const int* __restrict__ bIdx, int idxB,
         void* __restrict__ C0v, void* __restrict__ C1v,
         int K, int ldc, size_t aB, size_t bB, size_t cB) {
    extern __shared__ char smem[];
    constexpr uint32_t OFFB = (PASSES == 3 ? 2u : 1u) * PLANE;
    constexpr uint32_t STG  = (PASSES == 3 ? 4u : 2u) * PLANE;

    const int tid = threadIdx.x, bz = blockIdx.z;
    const int m0 = blockIdx.y * 128, n0 = blockIdx.x * 128;
    Ah += bz * aB + (size_t)m0 * K;
    if (PASSES == 3) Al += bz * aB + (size_t)m0 * K;
    const uint32_t s0 = s2u(smem);

    const int lr = tid >> 2, lg = tid & 3;
    const size_t go = (size_t)lr * K + lg * 8;
    size_t bgo;
    if (GATHB) {
        int r0 = bIdx[(size_t)bz * idxB + n0 + lr];
        bgo = (size_t)r0 * K + lg * 8;
    } else {
        Bh += bz * bB + (size_t)n0 * K;
        if (PASSES == 3) Bl += bz * bB + (size_t)n0 * K;
        bgo = go;
    }
    const uint32_t so = (uint32_t)(lr * SPAD + lg * 16);

    const int lane = tid & 31, wid = tid >> 5;
    const int wm = (wid & 3) * 32, wn = (wid >> 2) * 32;
    const int l8 = lane & 7, mid = lane >> 3;
    uint32_t aoff[2][2], boff[2][2];
#pragma unroll
    for (int mt = 0; mt < 2; mt++)
#pragma unroll
        for (int ks = 0; ks < 2; ks++)
            aoff[mt][ks] = (uint32_t)((wm + mt * 16 + (mid & 1) * 8 + l8) * SPAD
                                      + ((mid >> 1) * 8 + ks * 16) * 2);
#pragma unroll
    for (int p = 0; p < 2; p++)
#pragma unroll
        for (int ks = 0; ks < 2; ks++)
            boff[p][ks] = (uint32_t)(OFFB + (wn + p * 16 + (mid >> 1) * 8 + l8) * SPAD
                                     + ((mid & 1) * 8 + ks * 16) * 2);

    float acc[2][4][4];
    uint32_t acx[2][4][2];
#pragma unroll
    for (int mt = 0; mt < 2; mt++)
#pragma unroll
        for (int nt = 0; nt < 4; nt++) {
#pragma unroll
            for (int e = 0; e < 4; e++) acc[mt][nt][e] = 0.f;
            acx[mt][nt][0] = 0u; acx[mt][nt][1] = 0u;
        }

    const int nc = K >> 5;

#define LOADSTG(c) do { \
    uint32_t sb_ = s0 + ((c) & 3) * STG; \
    size_t ko_ = (size_t)(c) * 32; \
    cpa16h(sb_ + so,        Ah + go + ko_); \
    cpa16h(sb_ + OFFB + so, Bh + bgo + ko_); \
    if (PASSES == 3) { \
        cpa16h(sb_ + PLANE + so,        Al + go + ko_); \
        cpa16h(sb_ + OFFB + PLANE + so, Bl + bgo + ko_); \
    } \
    cpacommit(); \
} while (0)

    LOADSTG(0); LOADSTG(1); LOADSTG(2);

    for (int c = 0; c < nc; c++) {
        cpawait2();
        __syncthreads();
        if (c + 3 < nc) LOADSTG(c + 3); else cpacommit();
        const uint32_t sb = s0 + (c & 3) * STG;
#pragma unroll
        for (int ks = 0; ks < 2; ks++) {
            uint32_t fa[2][4], fb[2][4];
#pragma unroll
            for (int mt = 0; mt < 2; mt++) ldsm4(fa[mt], sb + aoff[mt][ks]);
#pragma unroll
            for (int p = 0; p < 2; p++) ldsm4(fb[p], sb + boff[p][ks]);
#pragma unroll
            for (int mt = 0; mt < 2; mt++)
#pragma unroll
                for (int nt = 0; nt < 4; nt++)
                    mma16f(acc[mt][nt], fa[mt], &fb[nt >> 1][(nt & 1) * 2]);
            if (PASSES == 3) {
                uint32_t fal[2][4], fbl[2][4];
#pragma unroll
                for (int p = 0; p < 2; p++) ldsm4(fbl[p], sb + boff[p][ks] + PLANE);
#pragma unroll
                for (int mt = 0; mt < 2; mt++)
#pragma unroll
                    for (int nt = 0; nt < 4; nt++)
                        mma16h(acx[mt][nt], fa[mt], &fbl[nt >> 1][(nt & 1) * 2]);
#pragma unroll
                for (int mt = 0; mt < 2; mt++) ldsm4(fal[mt], sb + aoff[mt][ks] + PLANE);
#pragma unroll
                for (int mt = 0; mt < 2; mt++)
#pragma unroll
                    for (int nt = 0; nt < 4; nt++)
                        mma16h(acx[mt][nt], fal[mt], &fb[nt >> 1][(nt & 1) * 2]);
            }
        }
    }
#undef LOADSTG

    const int qr = lane >> 2, qk = lane & 3;
#pragma unroll
    for (int mt = 0; mt < 2; mt++) {
#pragma unroll
        for (int nt = 0; nt < 4; nt++) {
            const int r = m0 + wm + mt * 16 + qr;
            const int cc = n0 + wn + nt * 8 + qk * 2;
            float v0, v1, v2, v3;
            if (PASSES == 3) {
                float2 x01 = __half22float2(*(__half2*)&acx[mt][nt][0]);
                float2 x23 = __half22float2(*(__half2*)&acx[mt][nt][1]);
                v0 = (acc[mt][nt][0] + x01.x) * INV_SCALE;
                v1 = (acc[mt][nt][1] + x01.y) * INV_SCALE;
                v2 = (acc[mt][nt][2] + x23.x) * INV_SCALE;
                v3 = (acc[mt][nt][3] + x23.y) * INV_SCALE;
            } else {
                v0 = acc[mt][nt][0] * INV_SCALE;
                v1 = acc[mt][nt][1] * INV_SCALE;
                v2 = acc[mt][nt][2] * INV_SCALE;
                v3 = acc[mt][nt][3] * INV_SCALE;
            }
            if (ACT) { v0 = gelu_f(v0); v1 = gelu_f(v1); v2 = gelu_f(v2); v3 = gelu_f(v3); }
            if (OUTMODE == 1) {
                __half* C0 = (__half*)C0v + bz * cB;
                __half* C1 = (__half*)C1v + bz * cB;
                __half h0, l0, h1, l1;
                split16(v0, h0, l0); split16(v1, h1, l1);
                *(__half2*)&C0[(size_t)r * ldc + cc] = __halves2half2(h0, h1);
                *(__half2*)&C1[(size_t)r * ldc + cc] = __halves2half2(l0, l1);
                split16(v2, h0, l0); split16(v3, h1, l1);
                *(__half2*)&C0[(size_t)(r + 8) * ldc + cc] = __halves2half2(h0, h1);
                *(__half2*)&C1[(size_t)(r + 8) * ldc + cc] = __halves2half2(l0, l1);
            } else if (OUTMODE == 2) {
                __half* C0 = (__half*)C0v + bz * cB;
                *(__half2*)&C0[(size_t)r * ldc + cc] =
                    __halves2half2(__float2half_rn(v0), __float2half_rn(v1));
                *(__half2*)&C0[(size_t)(r + 8) * ldc + cc] =
                    __halves2half2(__float2half_rn(v2), __float2half_rn(v3));
            } else {
                float* C0 = (float*)C0v + bz * cB;
                float2 w0 = {v0, v1}, w1 = {v2, v3};
                *(float2*)&C0[(size_t)r * ldc + cc] = w0;
                *(float2*)&C0[(size_t)(r + 8) * ldc + cc] = w1;
            }
        }
    }
}

// ---------------- launch 0: gcmax + split(x) + split(IP) fused ----------------
__global__ void k_prep0(const float* __restrict__ x, const float* __restrict__ IP) {
    int bx = blockIdx.x;
    if (bx < 16) {
        int b = bx >> 2, d = (bx & 3) * 256 + threadIdx.x;
        const float* p = x + (size_t)b * SS * DD + d;
        __half* ph = g_xh + (size_t)b * SS * DD + d;
        __half* pl = g_xl + (size_t)b * SS * DD + d;
        float m = -3.4e38f;
        for (int s = 0; s < SS; s++) {
            float v = p[(size_t)s * DD];
            m = fmaxf(m, v);
            __half h, l;
            split16(v, h, l);
            ph[(size_t)s * DD] = h;
            pl[(size_t)s * DD] = l;
        }
        g_gc[b * DD + d] = m;
    } else {
        size_t i = (size_t)(bx - 16) * 256 + threadIdx.x;
        float4 v = ((const float4*)IP)[i];
        __half hx, lx, hy, ly, hz, lz, hw, lw;
        split16(v.x * SCALE_B, hx, lx); split16(v.y * SCALE_B, hy, ly);
        split16(v.z * SCALE_B, hz, lz); split16(v.w * SCALE_B, hw, lw);
        ((__half2*)g_iph)[2 * i]     = __halves2half2(hx, hy);
        ((__half2*)g_iph)[2 * i + 1] = __halves2half2(hz, hw);
        ((__half2*)g_ipl)[2 * i]     = __halves2half2(lx, ly);
        ((__half2*)g_ipl)[2 * i + 1] = __halves2half2(lz, lw);
    }
}

// ---------------- launch 1: full router MLP + logits slice ----------------
__global__ void k_mlp_logits(const float* __restrict__ W1, const float* __restrict__ b1,
                             const float* __restrict__ lng, const float* __restrict__ lnb,
                             const float* __restrict__ W2, const float* __restrict__ b2,
                             const float* __restrict__ NK) {
    const int b = blockIdx.y;
    const int nb0 = blockIdx.x * (NIN / 16);
    __shared__ float sin[DD];
    __shared__ float sh[HH];
    __shared__ float sq[DR];
    __shared__ float red[8];
    __shared__ float smu, svar;
    const int tid = threadIdx.x, wid = tid >> 5, lane = tid & 31;

    for (int d = tid; d < DD; d += 256) sin[d] = g_gc[b * DD + d];
    __syncthreads();

    for (int o = wid; o < HH; o += 8) {
        float s = 0.f;
        for (int d = lane; d < DD; d += 32) s = fmaf(W1[(size_t)o * DD + d], sin[d], s);
#pragma unroll
        for (int off = 16; off; off >>= 1) s += __shfl_xor_sync(0xffffffffu, s, off);
        if (lane == 0) sh[o] = gelu_f(s + b1[o]);
    }
    __syncthreads();

    float v0 = sh[tid], v1 = sh[tid + 256];
    float s = v0 + v1;
#pragma unroll
    for (int off = 16; off; off >>= 1) s += __shfl_xor_sync(0xffffffffu, s, off);
    if (lane == 0) red[wid] = s;
    __syncthreads();
    if (tid == 0) { float t = 0.f; for (int w = 0; w < 8; w++) t += red[w]; smu = t / HH; }
    __syncthreads();
    float mu = smu;
    float d0 = v0 - mu, d1 = v1 - mu;
    float s2 = d0 * d0 + d1 * d1;
#pragma unroll
    for (int off = 16; off; off >>= 1) s2 += __shfl_xor_sync(0xffffffffu, s2, off);
    __syncthreads();
    if (lane == 0) red[wid] = s2;
    __syncthreads();
    if (tid == 0) { float t = 0.f; for (int w = 0; w < 8; w++) t += red[w]; svar = t / HH; }
    __syncthreads();
    float rstd = rsqrtf(svar + 1e-5f);
    sh[tid]       = d0 * rstd * lng[tid] + lnb[tid];
    sh[tid + 256] = d1 * rstd * lng[tid + 256] + lnb[tid + 256];
    __syncthreads();

    for (int o = wid; o < DR; o += 8) {
        float q = 0.f;
        for (int d = lane; d < HH; d += 32) q = fmaf(W2[(size_t)o * HH + d], sh[d], q);
#pragma unroll
        for (int off = 16; off; off >>= 1) q += __shfl_xor_sync(0xffffffffu, q, off);
        if (lane == 0) sq[o] = q + b2[o];
    }
    __syncthreads();

    for (int o = wid; o < NIN / 16; o += 8) {
        int oo = nb0 + o;
        float lg = 0.f;
        for (int d = lane; d < DR; d += 32) lg = fmaf(NK[(size_t)oo * DR + d], sq[d], lg);
#pragma unroll
        for (int off = 16; off; off >>= 1) lg += __shfl_xor_sync(0xffffffffu, lg, off);
        if (lane == 0) g_logits[(size_t)b * NIN + oo] = lg * 0.0625f;
    }
}

// ---------------- exact top-k set selection via counting rank ----------------
__global__ void k_select(const float* __restrict__ vals, int n, int k, int* __restrict__ idx) {
    int b = blockIdx.y;
    const float* v = vals + (size_t)b * n;
    int i = blockIdx.x * 256 + threadIdx.x;
    float vi = v[i];
    __shared__ float sv[256];
    int r = 0;
    for (int t0 = 0; t0 < n; t0 += 256) {
        sv[threadIdx.x] = v[t0 + threadIdx.x];
        __syncthreads();
#pragma unroll 8
        for (int t = 0; t < 256; t++) {
            float vj = sv[t];
            int j = t0 + t;
            r += (vj > vi) || (vj == vi && j < i);
        }
        __syncthreads();
    }
    if (r < k) idx[(size_t)b * k + r] = i;
}

// ---------------- sort selected index list ascending ----------------
__global__ void k_order(const int* __restrict__ in, int* __restrict__ outp, int k) {
    int b = blockIdx.y;
    const int* v = in + (size_t)b * k;
    int i = blockIdx.x * 256 + threadIdx.x;
    int vi = v[i];
    __shared__ int sv[256];
    int cnt = 0;
    for (int t0 = 0; t0 < k; t0 += 256) {
        sv[threadIdx.x] = v[t0 + threadIdx.x];
        __syncthreads();
#pragma unroll 8
        for (int t = 0; t < 256; t++) cnt += (sv[t] < vi);
        __syncthreads();
    }
    outp[(size_t)b * k + cnt] = vi;
}

// ---------------- standalone gather PW columns + scale + split (512 thr) ----------
__global__ void k_gatherW(const float* __restrict__ PW) {
    int b = blockIdx.z;
    int k0 = blockIdx.x * 512;
    int p0 = blockIdx.y * 32;
    __shared__ int si[512];
    si[threadIdx.x] = g_iidx2[(size_t)b * KIN + k0 + threadIdx.x];
    __syncthreads();
    int col = si[threadIdx.x];
#pragma unroll 4
    for (int pp = 0; pp < 32; pp++) {
        int p = p0 + pp;
        float v = PW[(size_t)p * NIN + col] * SCALE_B;
        __half h, l;
        split16(v, h, l);
        size_t o = ((size_t)b * NPROC + p) * KIN + k0 + threadIdx.x;
        g_wgh[o] = h;
        g_wgl[o] = l;
    }
}

// ---------------- scores[b][p] = mean_s proc[b][s][p] (fp16 proc) ----------------
__global__ void k_scores() {
    int b = blockIdx.y;
    int p = blockIdx.x * 256 + threadIdx.x;
    const __half* base = g_proch + (size_t)b * SS * NPROC + p;
    float s = 0.f;
    for (int t = 0; t < SS; t++) s += __half2float(base[(size_t)t * NPROC]);
    g_scores[b * NPROC + p] = s * (1.0f / SS);
}

// ---------------- fused: gathersp (65536 blocks) + po_t (8192 blocks) ----------
__global__ void k_gsp_pot(const float* __restrict__ PO) {
    int bid = blockIdx.x;
    if (bid < 65536) {
        int kx = (bid & 7) * 256 + threadIdx.x;
        int s = (bid >> 3) & 2047;
        int b = bid >> 14;
        int pi = g_pidx2[(size_t)b * KPROC + kx];
        g_sph[((size_t)b * SS + s) * KPROC + kx] =
            g_proch[((size_t)b * SS + s) * NPROC + pi];
    } else {
        __shared__ float t[32][33];
        int id = bid - 65536;
        int k0 = (id & 63) * 32;
        int d0 = ((id >> 6) & 31) * 32;
        int b = id >> 11;
        int tx = threadIdx.x & 31, ty = threadIdx.x >> 5;
        for (int i = ty; i < 32; i += 8) {
            int pi = g_pidx2[(size_t)b * KPROC + k0 + i];
            t[i][tx] = PO[(size_t)pi * DD + d0 + tx];
        }
        __syncthreads();
        for (int i = ty; i < 32; i += 8)
            g_poth[((size_t)b * DD + d0 + i) * KPROC + k0 + tx] =
                __float2half_rn(t[tx][i] * SCALE_B);
    }
}

// ---------------- host side ----------------
extern "C" void kernel_launch(void* const* d_in, const int* in_sizes, int n_in,
                              void* d_out, int out_size) {
    const float* x   = (const float*)d_in[0];
    const float* W1  = (const float*)d_in[1];
    const float* b1  = (const float*)d_in[2];
    const float* lng = (const float*)d_in[3];
    const float* lnb = (const float*)d_in[4];
    const float* W2  = (const float*)d_in[5];
    const float* b2  = (const float*)d_in[6];
    const float* NK  = (const float*)d_in[7];
    const float* IP  = (const float*)d_in[8];
    const float* PW  = (const float*)d_in[9];
    const float* PO  = (const float*)d_in[10];
    float* out = (float*)d_out;

    void *p_logits, *p_iidx, *p_iidx2, *p_pidx, *p_pidx2, *p_scores;
    void *p_xh, *p_xl, *p_iph, *p_ipl, *p_selh, *p_sell, *p_wgh, *p_wgl;
    void *p_proch, *p_sph, *p_poth;
    cudaGetSymbolAddress(&p_logits, g_logits);
    cudaGetSymbolAddress(&p_iidx, g_iidx);
    cudaGetSymbolAddress(&p_iidx2, g_iidx2);
    cudaGetSymbolAddress(&p_pidx, g_pidx);
    cudaGetSymbolAddress(&p_pidx2, g_pidx2);
    cudaGetSymbolAddress(&p_scores, g_scores);
    cudaGetSymbolAddress(&p_xh, g_xh);
    cudaGetSymbolAddress(&p_xl, g_xl);
    cudaGetSymbolAddress(&p_iph, g_iph);
    cudaGetSymbolAddress(&p_ipl, g_ipl);
    cudaGetSymbolAddress(&p_selh, g_selh);
    cudaGetSymbolAddress(&p_sell, g_sell);
    cudaGetSymbolAddress(&p_wgh, g_wgh);
    cudaGetSymbolAddress(&p_wgl, g_wgl);
    cudaGetSymbolAddress(&p_proch, g_proch);
    cudaGetSymbolAddress(&p_sph, g_sph);
    cudaGetSymbolAddress(&p_poth, g_poth);

    const int SM3 = 4 * 4 * PLANE;   // 163840
    const int SM1 = 4 * 2 * PLANE;   //  81920
    cudaFuncSetAttribute((const void*)&k_gemm_h<3, 1, 1, 1>, cudaFuncAttributeMaxDynamicSharedMemorySize, SM3);
    cudaFuncSetAttribute((const void*)&k_gemm_h<3, 1, 2, 0>, cudaFuncAttributeMaxDynamicSharedMemorySize, SM3);
    cudaFuncSetAttribute((const void*)&k_gemm_h<1, 0, 0, 0>, cudaFuncAttributeMaxDynamicSharedMemorySize, SM1);

    // 0) prep: gcmax + split(x) + split(IP)
    k_prep0<<<16 + (NIN * DD / 4) / 256, 256>>>(x, IP);

    // 1) router MLP + logits
    k_mlp_logits<<<dim3(16, BB), 256>>>(W1, b1, lng, lnb, W2, b2, NK);

    // 2) input selection (top-4096 of 8192)
    k_select<<<dim3(NIN / 256, BB), 256>>>((const float*)p_logits, NIN, KIN, (int*)p_iidx);

    // 3) sort index list ascending
    k_order<<<dim3(KIN / 256, BB), 256>>>((const int*)p_iidx, (int*)p_iidx2, KIN);

    // 4) sel GEMM
    k_gemm_h<3, 1, 1, 1><<<dim3(KIN / 128, SS / 128, BB), 512, SM3>>>(
        (const __half*)p_xh, (const __half*)p_xl, (const __half*)p_iph, (const __half*)p_ipl,
        (const int*)p_iidx2, KIN, p_selh, p_sell, DD, KIN,
        (size_t)SS * DD, 0, (size_t)SS * KIN);

    // 5) Wg gather + split (standalone, 512-thread blocks)
    k_gatherW<<<dim3(KIN / 512, NPROC / 32, BB), 512>>>(PW);

    // 6) proc GEMM -> fp16 proc
    k_gemm_h<3, 1, 2, 0><<<dim3(NPROC / 128, SS / 128, BB), 512, SM3>>>(
        (const __half*)p_selh, (const __half*)p_sell, (const __half*)p_wgh, (const __half*)p_wgl,
        nullptr, 0, p_proch, nullptr, KIN, NPROC,
        (size_t)SS * KIN, (size_t)NPROC * KIN, (size_t)SS * NPROC);

    // 7-9) process selection (sorted)
    k_scores<<<dim3(NPROC / 256, BB), 256>>>();
    k_select<<<dim3(NPROC / 256, BB), 256>>>((const float*)p_scores, NPROC, KPROC, (int*)p_pidx);
    k_order<<<dim3(KPROC / 256, BB), 256>>>((const int*)p_pidx, (int*)p_pidx2, KPROC);

    // 10) fused gathersp + po_t
    k_gsp_pot<<<65536 + 8192, 256>>>(PO);

    // 11) out GEMM, 1-pass fp16
    k_gemm_h<1, 0, 0, 0><<<dim3(DD / 128, SS / 128, BB), 512, SM1>>>(
        (const __half*)p_sph, (const __half*)p_sph, (const __half*)p_poth, (const __half*)p_poth,
        nullptr, 0, out, nullptr, KPROC, DD,
        (size_t)SS * KPROC, (size_t)DD * KPROC, (size_t)SS * DD);
}

// round 14
// speedup vs baseline: 1.0450x; 1.0336x over previous
#include <cuda_runtime.h>
#include <cuda_fp16.h>
#include <math.h>
#include <stdint.h>

#define BB     4
#define SS     2048
#define DD     1024
#define NIN    8192
#define NPROC  4096
#define DR     256
#define HH     512
#define KIN    4096
#define KPROC  2048

#define SCALE_B   4096.0f
#define INV_SCALE 2.44140625e-4f

// ---------------- scratch (static device memory; no allocs) ----------------
__device__ float g_gc[BB * DD];
__device__ float g_logits[BB * NIN];
__device__ int   g_rank[BB * NIN];          // partial ranks (int, atomicAdd)
__device__ int   g_iidx2[BB * KIN];         // ascending selected input idx
__device__ int   g_pidx2[BB * KPROC];       // ascending selected proc idx
__device__ float g_scores[BB * NPROC];
__device__ float g_scorep[16 * BB * NPROC]; // per-m-tile partial column sums

__align__(16) __device__ __half g_xh[(size_t)BB * SS * DD];
__align__(16) __device__ __half g_xl[(size_t)BB * SS * DD];
__align__(16) __device__ __half g_iph[(size_t)NIN * DD];
__align__(16) __device__ __half g_ipl[(size_t)NIN * DD];
__align__(16) __device__ __half g_selh[(size_t)BB * SS * KIN];
__align__(16) __device__ __half g_sell[(size_t)BB * SS * KIN];
__align__(16) __device__ __half g_wgh[(size_t)BB * NPROC * KIN];
__align__(16) __device__ __half g_wgl[(size_t)BB * NPROC * KIN];
__align__(16) __device__ __half g_sph[(size_t)BB * SS * KPROC];
__align__(16) __device__ __half g_poth[(size_t)BB * DD * KPROC];
__align__(16) __device__ __half g_proch[(size_t)BB * SS * NPROC];

__device__ __forceinline__ float gelu_f(float x) {
    return 0.5f * x * (1.0f + erff(x * 0.70710678118654752440f));
}
__device__ __forceinline__ void split16(float v, __half& h, __half& l) {
    h = __float2half_rn(v);
    l = __float2half_rn(v - __half2float(h));
}

__device__ __forceinline__ uint32_t s2u(const void* p) {
    uint32_t a;
    asm("{ .reg .u64 t; cvta.to.shared.u64 t, %1; cvt.u32.u64 %0, t; }" : "=r"(a) : "l"(p));
    return a;
}
__device__ __forceinline__ void cpa16h(uint32_t dst, const __half* src) {
    asm volatile("cp.async.cg.shared.global [%0], [%1], 16;" :: "r"(dst), "l"(src));
}
__device__ __forceinline__ void cpacommit() { asm volatile("cp.async.commit_group;" ::: "memory"); }
__device__ __forceinline__ void cpawait2()  { asm volatile("cp.async.wait_group 2;" ::: "memory"); }

__device__ __forceinline__ void ldsm4(uint32_t* r, uint32_t a) {
    asm volatile("ldmatrix.sync.aligned.m8n8.x4.shared.b16 {%0,%1,%2,%3}, [%4];"
        : "=r"(r[0]), "=r"(r[1]), "=r"(r[2]), "=r"(r[3]) : "r"(a));
}
__device__ __forceinline__ void mma16f(float* c, const uint32_t* a, const uint32_t* b) {
    asm volatile("mma.sync.aligned.m16n8k16.row.col.f32.f16.f16.f32 "
        "{%0,%1,%2,%3}, {%4,%5,%6,%7}, {%8,%9}, {%0,%1,%2,%3};"
        : "+f"(c[0]), "+f"(c[1]), "+f"(c[2]), "+f"(c[3])
        : "r"(a[0]), "r"(a[1]), "r"(a[2]), "r"(a[3]), "r"(b[0]), "r"(b[1]));
}
__device__ __forceinline__ void mma16h(uint32_t* c, const uint32_t* a, const uint32_t* b) {
    asm volatile("mma.sync.aligned.m16n8k16.row.col.f16.f16.f16.f16 "
        "{%0,%1}, {%2,%3,%4,%5}, {%6,%7}, {%0,%1};"
        : "+r"(c[0]), "+r"(c[1])
        : "r"(a[0]), "r"(a[1]), "r"(a[2]), "r"(a[3]), "r"(b[0]), "r"(b[1]));
}

// ===== fp16 split GEMM: C[128m x 128n], 512 threads, 16 warps (4x4), 32x32/warp =====
// PASSES=3: AhBh(f32acc) + (AhBl + AlBh)(f16acc). PASSES=1: AhBh only.
// OUTMODE: 0 = fp32, 1 = fp16 hi/lo split planes, 2 = fp16 plane + score partials.
#define SPAD   80
#define PLANE  10240               // 128 rows * 80B

template <int PASSES, int ACT, int OUTMODE, int GATHB>
__global__ void __launch_bounds__(512, 1)
k_gemm_h(const __half* __restrict__ Ah, const __half* __restrict__ Al,
         const __half* __restrict__ Bh, const __half* __restrict__ Bl,
         const int* __restrict__ bIdx, int idxB,
         void* __restrict__ C0v, void* __restrict__ C1v,
         int K, int ldc, size_t aB, size_t bB, size_t cB) {
    extern __shared__ char smem[];
    constexpr uint32_t OFFB = (PASSES == 3 ? 2u : 1u) * PLANE;
    constexpr uint32_t STG  = (PASSES == 3 ? 4u : 2u) * PLANE;

    const int tid = threadIdx.x, bz = blockIdx.z;
    const int m0 = blockIdx.y * 128, n0 = blockIdx.x * 128;
    Ah += bz * aB + (size_t)m0 * K;
    if (PASSES == 3) Al += bz * aB + (size_t)m0 * K;
    const uint32_t s0 = s2u(smem);

    const int lr = tid >> 2, lg = tid & 3;
    const size_t go = (size_t)lr * K + lg * 8;
    size_t bgo;
    if (GATHB) {
        int r0 = bIdx[(size_t)bz * idxB + n0 + lr];
        bgo = (size_t)r0 * K + lg * 8;
    } else {
        Bh += bz * bB + (size_t)n0 * K;
        if (PASSES == 3) Bl += bz * bB + (size_t)n0 * K;
        bgo = go;
    }
    const uint32_t so = (uint32_t)(lr * SPAD + lg * 16);

    const int lane = tid & 31, wid = tid >> 5;
    const int wm = (wid & 3) * 32, wn = (wid >> 2) * 32;
    const int l8 = lane & 7, mid = lane >> 3;
    uint32_t aoff[2][2], boff[2][2];
#pragma unroll
    for (int mt = 0; mt < 2; mt++)
#pragma unroll
        for (int ks = 0; ks < 2; ks++)
            aoff[mt][ks] = (uint32_t)((wm + mt * 16 + (mid & 1) * 8 + l8) * SPAD
                                      + ((mid >> 1) * 8 + ks * 16) * 2);
#pragma unroll
    for (int p = 0; p < 2; p++)
#pragma unroll
        for (int ks = 0; ks < 2; ks++)
            boff[p][ks] = (uint32_t)(OFFB + (wn + p * 16 + (mid >> 1) * 8 + l8) * SPAD
                                     + ((mid & 1) * 8 + ks * 16) * 2);

    float acc[2][4][4];
    uint32_t acx[2][4][2];
#pragma unroll
    for (int mt = 0; mt < 2; mt++)
#pragma unroll
        for (int nt = 0; nt < 4; nt++) {
#pragma unroll
            for (int e = 0; e < 4; e++) acc[mt][nt][e] = 0.f;
            acx[mt][nt][0] = 0u; acx[mt][nt][1] = 0u;
        }

    const int nc = K >> 5;

#define LOADSTG(c) do { \
    uint32_t sb_ = s0 + ((c) & 3) * STG; \
    size_t ko_ = (size_t)(c) * 32; \
    cpa16h(sb_ + so,        Ah + go + ko_); \
    cpa16h(sb_ + OFFB + so, Bh + bgo + ko_); \
    if (PASSES == 3) { \
        cpa16h(sb_ + PLANE + so,        Al + go + ko_); \
        cpa16h(sb_ + OFFB + PLANE + so, Bl + bgo + ko_); \
    } \
    cpacommit(); \
} while (0)

    LOADSTG(0); LOADSTG(1); LOADSTG(2);

    for (int c = 0; c < nc; c++) {
        cpawait2();
        __syncthreads();
        if (c + 3 < nc) LOADSTG(c + 3); else cpacommit();
        const uint32_t sb = s0 + (c & 3) * STG;
#pragma unroll
        for (int ks = 0; ks < 2; ks++) {
            uint32_t fa[2][4], fb[2][4];
#pragma unroll
            for (int mt = 0; mt < 2; mt++) ldsm4(fa[mt], sb + aoff[mt][ks]);
#pragma unroll
            for (int p = 0; p < 2; p++) ldsm4(fb[p], sb + boff[p][ks]);
#pragma unroll
            for (int mt = 0; mt < 2; mt++)
#pragma unroll
                for (int nt = 0; nt < 4; nt++)
                    mma16f(acc[mt][nt], fa[mt], &fb[nt >> 1][(nt & 1) * 2]);
            if (PASSES == 3) {
                uint32_t fal[2][4], fbl[2][4];
#pragma unroll
                for (int p = 0; p < 2; p++) ldsm4(fbl[p], sb + boff[p][ks] + PLANE);
#pragma unroll
                for (int mt = 0; mt < 2; mt++)
#pragma unroll
                    for (int nt = 0; nt < 4; nt++)
                        mma16h(acx[mt][nt], fa[mt], &fbl[nt >> 1][(nt & 1) * 2]);
#pragma unroll
                for (int mt = 0; mt < 2; mt++) ldsm4(fal[mt], sb + aoff[mt][ks] + PLANE);
#pragma unroll
                for (int mt = 0; mt < 2; mt++)
#pragma unroll
                    for (int nt = 0; nt < 4; nt++)
                        mma16h(acx[mt][nt], fal[mt], &fb[nt >> 1][(nt & 1) * 2]);
            }
        }
    }
#undef LOADSTG

    const int qr = lane >> 2, qk = lane & 3;
    float csum[4][2];
    if (OUTMODE == 2) {
#pragma unroll
        for (int nt = 0; nt < 4; nt++) { csum[nt][0] = 0.f; csum[nt][1] = 0.f; }
    }
#pragma unroll
    for (int mt = 0; mt < 2; mt++) {
#pragma unroll
        for (int nt = 0; nt < 4; nt++) {
            const int r = m0 + wm + mt * 16 + qr;
            const int cc = n0 + wn + nt * 8 + qk * 2;
            float v0, v1, v2, v3;
            if (PASSES == 3) {
                float2 x01 = __half22float2(*(__half2*)&acx[mt][nt][0]);
                float2 x23 = __half22float2(*(__half2*)&acx[mt][nt][1]);
                v0 = (acc[mt][nt][0] + x01.x) * INV_SCALE;
                v1 = (acc[mt][nt][1] + x01.y) * INV_SCALE;
                v2 = (acc[mt][nt][2] + x23.x) * INV_SCALE;
                v3 = (acc[mt][nt][3] + x23.y) * INV_SCALE;
            } else {
                v0 = acc[mt][nt][0] * INV_SCALE;
                v1 = acc[mt][nt][1] * INV_SCALE;
                v2 = acc[mt][nt][2] * INV_SCALE;
                v3 = acc[mt][nt][3] * INV_SCALE;
            }
            if (ACT) { v0 = gelu_f(v0); v1 = gelu_f(v1); v2 = gelu_f(v2); v3 = gelu_f(v3); }
            if (OUTMODE == 1) {
                __half* C0 = (__half*)C0v + bz * cB;
                __half* C1 = (__half*)C1v + bz * cB;
                __half h0, l0, h1, l1;
                split16(v0, h0, l0); split16(v1, h1, l1);
                *(__half2*)&C0[(size_t)r * ldc + cc] = __halves2half2(h0, h1);
                *(__half2*)&C1[(size_t)r * ldc + cc] = __halves2half2(l0, l1);
                split16(v2, h0, l0); split16(v3, h1, l1);
                *(__half2*)&C0[(size_t)(r + 8) * ldc + cc] = __halves2half2(h0, h1);
                *(__half2*)&C1[(size_t)(r + 8) * ldc + cc] = __halves2half2(l0, l1);
            } else if (OUTMODE == 2) {
                __half* C0 = (__half*)C0v + bz * cB;
                *(__half2*)&C0[(size_t)r * ldc + cc] =
                    __halves2half2(__float2half_rn(v0), __float2half_rn(v1));
                *(__half2*)&C0[(size_t)(r + 8) * ldc + cc] =
                    __halves2half2(__float2half_rn(v2), __float2half_rn(v3));
                csum[nt][0] += v0 + v2;
                csum[nt][1] += v1 + v3;
            } else {
                float* C0 = (float*)C0v + bz * cB;
                float2 w0 = {v0, v1}, w1 = {v2, v3};
                *(float2*)&C0[(size_t)r * ldc + cc] = w0;
                *(float2*)&C0[(size_t)(r + 8) * ldc + cc] = w1;
            }
        }
    }

    if (OUTMODE == 2) {
        // deterministic column-sum partials: reduce over qr lanes, then over the
        // 4 m-warps per n-window via smem, one write per column per CTA.
        float* sbuf = (float*)smem;   // stage 0 area; last chunk used stage (nc-1)&3 == 3
        __syncthreads();
#pragma unroll
        for (int nt = 0; nt < 4; nt++)
#pragma unroll
            for (int pr = 0; pr < 2; pr++) {
                float s = csum[nt][pr];
                s += __shfl_xor_sync(0xffffffffu, s, 4);
                s += __shfl_xor_sync(0xffffffffu, s, 8);
                s += __shfl_xor_sync(0xffffffffu, s, 16);
                if (qr == 0) sbuf[wid * 32 + nt * 8 + qk * 2 + pr] = s;
            }
        __syncthreads();
        if (tid < 128) {
            int g = tid >> 5, c32 = tid & 31;
            float tot = sbuf[(g * 4 + 0) * 32 + c32] + sbuf[(g * 4 + 1) * 32 + c32]
                      + sbuf[(g * 4 + 2) * 32 + c32] + sbuf[(g * 4 + 3) * 32 + c32];
            g_scorep[((size_t)bz * 16 + blockIdx.y) * NPROC + n0 + tid] = tot;
        }
    }
}

// ---------------- launch 0: gcmax + split(x) + split(IP) + zero rank ----------
__global__ void k_prep0(const float* __restrict__ x, const float* __restrict__ IP) {
    int bx = blockIdx.x;
    if (bx < 16) {
        // zero input-stage rank buffer (BB*NIN = 32768 ints; 4096 threads x 8)
        int zi = (bx * 256 + threadIdx.x) * 8;
#pragma unroll
        for (int q = 0; q < 8; q++) g_rank[zi + q] = 0;

        int b = bx >> 2, d = (bx & 3) * 256 + threadIdx.x;
        const float* p = x + (size_t)b * SS * DD + d;
        __half* ph = g_xh + (size_t)b * SS * DD + d;
        __half* pl = g_xl + (size_t)b * SS * DD + d;
        float m = -3.4e38f;
        for (int s = 0; s < SS; s++) {
            float v = p[(size_t)s * DD];
            m = fmaxf(m, v);
            __half h, l;
            split16(v, h, l);
            ph[(size_t)s * DD] = h;
            pl[(size_t)s * DD] = l;
        }
        g_gc[b * DD + d] = m;
    } else {
        size_t i = (size_t)(bx - 16) * 256 + threadIdx.x;
        float4 v = ((const float4*)IP)[i];
        __half hx, lx, hy, ly, hz, lz, hw, lw;
        split16(v.x * SCALE_B, hx, lx); split16(v.y * SCALE_B, hy, ly);
        split16(v.z * SCALE_B, hz, lz); split16(v.w * SCALE_B, hw, lw);
        ((__half2*)g_iph)[2 * i]     = __halves2half2(hx, hy);
        ((__half2*)g_iph)[2 * i + 1] = __halves2half2(hz, hw);
        ((__half2*)g_ipl)[2 * i]     = __halves2half2(lx, ly);
        ((__half2*)g_ipl)[2 * i + 1] = __halves2half2(lz, lw);
    }
}

// ---------------- launch 1: full router MLP + logits slice ----------------
__global__ void k_mlp_logits(const float* __restrict__ W1, const float* __restrict__ b1,
                             const float* __restrict__ lng, const float* __restrict__ lnb,
                             const float* __restrict__ W2, const float* __restrict__ b2,
                             const float* __restrict__ NK) {
    const int b = blockIdx.y;
    const int nb0 = blockIdx.x * (NIN / 16);
    __shared__ float sin[DD];
    __shared__ float sh[HH];
    __shared__ float sq[DR];
    __shared__ float red[8];
    __shared__ float smu, svar;
    const int tid = threadIdx.x, wid = tid >> 5, lane = tid & 31;

    for (int d = tid; d < DD; d += 256) sin[d] = g_gc[b * DD + d];
    __syncthreads();

    for (int o = wid; o < HH; o += 8) {
        float s = 0.f;
        for (int d = lane; d < DD; d += 32) s = fmaf(W1[(size_t)o * DD + d], sin[d], s);
#pragma unroll
        for (int off = 16; off; off >>= 1) s += __shfl_xor_sync(0xffffffffu, s, off);
        if (lane == 0) sh[o] = gelu_f(s + b1[o]);
    }
    __syncthreads();

    float v0 = sh[tid], v1 = sh[tid + 256];
    float s = v0 + v1;
#pragma unroll
    for (int off = 16; off; off >>= 1) s += __shfl_xor_sync(0xffffffffu, s, off);
    if (lane == 0) red[wid] = s;
    __syncthreads();
    if (tid == 0) { float t = 0.f; for (int w = 0; w < 8; w++) t += red[w]; smu = t / HH; }
    __syncthreads();
    float mu = smu;
    float d0 = v0 - mu, d1 = v1 - mu;
    float s2 = d0 * d0 + d1 * d1;
#pragma unroll
    for (int off = 16; off; off >>= 1) s2 += __shfl_xor_sync(0xffffffffu, s2, off);
    __syncthreads();
    if (lane == 0) red[wid] = s2;
    __syncthreads();
    if (tid == 0) { float t = 0.f; for (int w = 0; w < 8; w++) t += red[w]; svar = t / HH; }
    __syncthreads();
    float rstd = rsqrtf(svar + 1e-5f);
    sh[tid]       = d0 * rstd * lng[tid] + lnb[tid];
    sh[tid + 256] = d1 * rstd * lng[tid + 256] + lnb[tid + 256];
    __syncthreads();

    for (int o = wid; o < DR; o += 8) {
        float q = 0.f;
        for (int d = lane; d < HH; d += 32) q = fmaf(W2[(size_t)o * HH + d], sh[d], q);
#pragma unroll
        for (int off = 16; off; off >>= 1) q += __shfl_xor_sync(0xffffffffu, q, off);
        if (lane == 0) sq[o] = q + b2[o];
    }
    __syncthreads();

    for (int o = wid; o < NIN / 16; o += 8) {
        int oo = nb0 + o;
        float lg = 0.f;
        for (int d = lane; d < DR; d += 32) lg = fmaf(NK[(size_t)oo * DR + d], sq[d], lg);
#pragma unroll
        for (int off = 16; off; off >>= 1) lg += __shfl_xor_sync(0xffffffffu, lg, off);
        if (lane == 0) g_logits[(size_t)b * NIN + oo] = lg * 0.0625f;
    }
}

// ---------------- partial rank counting (sliced 8x, int atomics) ----------------
// rank(i) = #{j : v[j] > v[i]  ||  (v[j]==v[i] && j<i)}  -- matches lax.top_k
__global__ void k_selrank(const float* __restrict__ vals, int n, int* __restrict__ rank) {
    int b = blockIdx.z;
    const float* v = vals + (size_t)b * n;
    int i = blockIdx.x * 256 + threadIdx.x;
    float vi = v[i];
    int t0beg = blockIdx.y * (n >> 3);
    int t0end = t0beg + (n >> 3);
    __shared__ float sv[256];
    int r = 0;
    for (int t0 = t0beg; t0 < t0end; t0 += 256) {
        sv[threadIdx.x] = v[t0 + threadIdx.x];
        __syncthreads();
#pragma unroll 8
        for (int t = 0; t < 256; t++) {
            float vj = sv[t];
            int j = t0 + t;
            r += (vj > vi) || (vj == vi && j < i);
        }
        __syncthreads();
    }
    atomicAdd(&rank[(size_t)b * n + i], r);
}

// ---------------- compact: rank<k -> ascending index list ----------------
__global__ void k_compact(const int* __restrict__ rank, int n, int k, int* __restrict__ outp) {
    int b = blockIdx.x;
    const int* rk = rank + (size_t)b * n;
    int* op = outp + (size_t)b * k;
    __shared__ int warpCnt[32];
    __shared__ int sbase;
    int tid = threadIdx.x, lane = tid & 31, wid = tid >> 5;
    if (tid == 0) sbase = 0;
    __syncthreads();
    for (int c0 = 0; c0 < n; c0 += 1024) {
        int i = c0 + tid;
        int f = (rk[i] < k) ? 1 : 0;
        unsigned bal = __ballot_sync(0xffffffffu, f);
        if (lane == 0) warpCnt[wid] = __popc(bal);
        __syncthreads();
        int prefix = sbase;
        for (int w = 0; w < wid; w++) prefix += warpCnt[w];
        prefix += __popc(bal & ((1u << lane) - 1));
        if (f) op[prefix] = i;
        __syncthreads();
        if (tid == 0) { int t = 0; for (int w = 0; w < 32; w++) t += warpCnt[w]; sbase += t; }
        __syncthreads();
    }
}

// ---------------- standalone gather PW columns + scale + split (512 thr) ----------
__global__ void k_gatherW(const float* __restrict__ PW) {
    int b = blockIdx.z;
    int k0 = blockIdx.x * 512;
    int p0 = blockIdx.y * 32;
    __shared__ int si[512];
    si[threadIdx.x] = g_iidx2[(size_t)b * KIN + k0 + threadIdx.x];
    __syncthreads();
    int col = si[threadIdx.x];
#pragma unroll 4
    for (int pp = 0; pp < 32; pp++) {
        int p = p0 + pp;
        float v = PW[(size_t)p * NIN + col] * SCALE_B;
        __half h, l;
        split16(v, h, l);
        size_t o = ((size_t)b * NPROC + p) * KIN + k0 + threadIdx.x;
        g_wgh[o] = h;
        g_wgl[o] = l;
    }
}

// ---------------- reduce 16 score partials -> scores; zero proc rank ----------
__global__ void k_scores2() {
    int b = blockIdx.y;
    int p = blockIdx.x * 256 + threadIdx.x;
    float s = 0.f;
#pragma unroll
    for (int t = 0; t < 16; t++) s += g_scorep[((size_t)b * 16 + t) * NPROC + p];
    g_scores[b * NPROC + p] = s * (1.0f / SS);
    g_rank[(size_t)b * NPROC + p] = 0;
}

// ---------------- fused: gathersp (65536 blocks) + po_t (8192 blocks) ----------
__global__ void k_gsp_pot(const float* __restrict__ PO) {
    int bid = blockIdx.x;
    if (bid < 65536) {
        int kx = (bid & 7) * 256 + threadIdx.x;
        int s = (bid >> 3) & 2047;
        int b = bid >> 14;
        int pi = g_pidx2[(size_t)b * KPROC + kx];
        g_sph[((size_t)b * SS + s) * KPROC + kx] =
            g_proch[((size_t)b * SS + s) * NPROC + pi];
    } else {
        __shared__ float t[32][33];
        int id = bid - 65536;
        int k0 = (id & 63) * 32;
        int d0 = ((id >> 6) & 31) * 32;
        int b = id >> 11;
        int tx = threadIdx.x & 31, ty = threadIdx.x >> 5;
        for (int i = ty; i < 32; i += 8) {
            int pi = g_pidx2[(size_t)b * KPROC + k0 + i];
            t[i][tx] = PO[(size_t)pi * DD + d0 + tx];
        }
        __syncthreads();
        for (int i = ty; i < 32; i += 8)
            g_poth[((size_t)b * DD + d0 + i) * KPROC + k0 + tx] =
                __float2half_rn(t[tx][i] * SCALE_B);
    }
}

// ---------------- host side ----------------
extern "C" void kernel_launch(void* const* d_in, const int* in_sizes, int n_in,
                              void* d_out, int out_size) {
    const float* x   = (const float*)d_in[0];
    const float* W1  = (const float*)d_in[1];
    const float* b1  = (const float*)d_in[2];
    const float* lng = (const float*)d_in[3];
    const float* lnb = (const float*)d_in[4];
    const float* W2  = (const float*)d_in[5];
    const float* b2  = (const float*)d_in[6];
    const float* NK  = (const float*)d_in[7];
    const float* IP  = (const float*)d_in[8];
    const float* PW  = (const float*)d_in[9];
    const float* PO  = (const float*)d_in[10];
    float* out = (float*)d_out;

    void *p_logits, *p_rank, *p_iidx2, *p_pidx2, *p_scores;
    void *p_xh, *p_xl, *p_iph, *p_ipl, *p_selh, *p_sell, *p_wgh, *p_wgl;
    void *p_proch, *p_sph, *p_poth;
    cudaGetSymbolAddress(&p_logits, g_logits);
    cudaGetSymbolAddress(&p_rank, g_rank);
    cudaGetSymbolAddress(&p_iidx2, g_iidx2);
    cudaGetSymbolAddress(&p_pidx2, g_pidx2);
    cudaGetSymbolAddress(&p_scores, g_scores);
    cudaGetSymbolAddress(&p_xh, g_xh);
    cudaGetSymbolAddress(&p_xl, g_xl);
    cudaGetSymbolAddress(&p_iph, g_iph);
    cudaGetSymbolAddress(&p_ipl, g_ipl);
    cudaGetSymbolAddress(&p_selh, g_selh);
    cudaGetSymbolAddress(&p_sell, g_sell);
    cudaGetSymbolAddress(&p_wgh, g_wgh);
    cudaGetSymbolAddress(&p_wgl, g_wgl);
    cudaGetSymbolAddress(&p_proch, g_proch);
    cudaGetSymbolAddress(&p_sph, g_sph);
    cudaGetSymbolAddress(&p_poth, g_poth);

    const int SM3 = 4 * 4 * PLANE;   // 163840
    const int SM1 = 4 * 2 * PLANE;   //  81920
    cudaFuncSetAttribute((const void*)&k_gemm_h<3, 1, 1, 1>, cudaFuncAttributeMaxDynamicSharedMemorySize, SM3);
    cudaFuncSetAttribute((const void*)&k_gemm_h<3, 1, 2, 0>, cudaFuncAttributeMaxDynamicSharedMemorySize, SM3);
    cudaFuncSetAttribute((const void*)&k_gemm_h<1, 0, 0, 0>, cudaFuncAttributeMaxDynamicSharedMemorySize, SM1);

    // 0) prep: gcmax + split(x) + split(IP) + zero input rank
    k_prep0<<<16 + (NIN * DD / 4) / 256, 256>>>(x, IP);

    // 1) router MLP + logits
    k_mlp_logits<<<dim3(16, BB), 256>>>(W1, b1, lng, lnb, W2, b2, NK);

    // 2-3) input selection: sliced rank count + compaction (ascending)
    k_selrank<<<dim3(NIN / 256, 8, BB), 256>>>((const float*)p_logits, NIN, (int*)p_rank);
    k_compact<<<BB, 1024>>>((const int*)p_rank, NIN, KIN, (int*)p_iidx2);

    // 4) sel GEMM
    k_gemm_h<3, 1, 1, 1><<<dim3(KIN / 128, SS / 128, BB), 512, SM3>>>(
        (const __half*)p_xh, (const __half*)p_xl, (const __half*)p_iph, (const __half*)p_ipl,
        (const int*)p_iidx2, KIN, p_selh, p_sell, DD, KIN,
        (size_t)SS * DD, 0, (size_t)SS * KIN);

    // 5) Wg gather + split
    k_gatherW<<<dim3(KIN / 512, NPROC / 32, BB), 512>>>(PW);

    // 6) proc GEMM -> fp16 proc + per-m-tile score partials
    k_gemm_h<3, 1, 2, 0><<<dim3(NPROC / 128, SS / 128, BB), 512, SM3>>>(
        (const __half*)p_selh, (const __half*)p_sell, (const __half*)p_wgh, (const __half*)p_wgl,
        nullptr, 0, p_proch, nullptr, KIN, NPROC,
        (size_t)SS * KIN, (size_t)NPROC * KIN, (size_t)SS * NPROC);

    // 7) reduce score partials + zero proc rank
    k_scores2<<<dim3(NPROC / 256, BB), 256>>>();

    // 8-9) process selection
    k_selrank<<<dim3(NPROC / 256, 8, BB), 256>>>((const float*)p_scores, NPROC, (int*)p_rank);
    k_compact<<<BB, 1024>>>((const int*)p_rank, NPROC, KPROC, (int*)p_pidx2);

    // 10) fused gathersp + po_t
    k_gsp_pot<<<65536 + 8192, 256>>>(PO);

    // 11) out GEMM, 1-pass fp16
    k_gemm_h<1, 0, 0, 0><<<dim3(DD / 128, SS / 128, BB), 512, SM1>>>(
        (const __half*)p_sph, (const __half*)p_sph, (const __half*)p_poth, (const __half*)p_poth,
        nullptr, 0, out, nullptr, KPROC, DD,
        (size_t)SS * KPROC, (size_t)DD * KPROC, (size_t)SS * DD);
}

// round 15
// speedup vs baseline: 1.0870x; 1.0402x over previous
#include <cuda_runtime.h>
#include <cuda_fp16.h>
#include <math.h>
#include <stdint.h>

#define BB     4
#define SS     2048
#define DD     1024
#define NIN    8192
#define NPROC  4096
#define DR     256
#define HH     512
#define KIN    4096
#define KPROC  2048

#define SCALE_B   4096.0f
#define INV_SCALE 2.44140625e-4f

// ---------------- scratch (static device memory; no allocs) ----------------
__device__ float g_gc[BB * DD];
__device__ float g_logits[BB * NIN];
__device__ int   g_rank[BB * NIN];
__device__ int   g_iidx2[BB * KIN];
__device__ int   g_pidx2[BB * KPROC];
__device__ float g_scores[BB * NPROC];
__device__ float g_scorep[16 * BB * NPROC];

__align__(16) __device__ __half g_xh[(size_t)BB * SS * DD];
__align__(16) __device__ __half g_xl[(size_t)BB * SS * DD];
__align__(16) __device__ __half g_iph[(size_t)NIN * DD];
__align__(16) __device__ __half g_ipl[(size_t)NIN * DD];
__align__(16) __device__ __half g_selh[(size_t)BB * SS * KIN];
__align__(16) __device__ __half g_sell[(size_t)BB * SS * KIN];
__align__(16) __device__ __half g_wgh[(size_t)BB * NPROC * KIN];
__align__(16) __device__ __half g_wgl[(size_t)BB * NPROC * KIN];
__align__(16) __device__ __half g_sph[(size_t)BB * SS * KPROC];
__align__(16) __device__ __half g_poth[(size_t)BB * DD * KPROC];
__align__(16) __device__ __half g_proch[(size_t)BB * SS * NPROC];

__device__ __forceinline__ float gelu_f(float x) {
    return 0.5f * x * (1.0f + erff(x * 0.70710678118654752440f));
}
__device__ __forceinline__ void split16(float v, __half& h, __half& l) {
    h = __float2half_rn(v);
    l = __float2half_rn(v - __half2float(h));
}

__device__ __forceinline__ uint32_t s2u(const void* p) {
    uint32_t a;
    asm("{ .reg .u64 t; cvta.to.shared.u64 t, %1; cvt.u32.u64 %0, t; }" : "=r"(a) : "l"(p));
    return a;
}
__device__ __forceinline__ void cpa16h(uint32_t dst, const __half* src) {
    asm volatile("cp.async.cg.shared.global [%0], [%1], 16;" :: "r"(dst), "l"(src));
}
__device__ __forceinline__ void cpacommit() { asm volatile("cp.async.commit_group;" ::: "memory"); }
__device__ __forceinline__ void cpawait2()  { asm volatile("cp.async.wait_group 2;" ::: "memory"); }

__device__ __forceinline__ void ldsm4(uint32_t* r, uint32_t a) {
    asm volatile("ldmatrix.sync.aligned.m8n8.x4.shared.b16 {%0,%1,%2,%3}, [%4];"
        : "=r"(r[0]), "=r"(r[1]), "=r"(r[2]), "=r"(r[3]) : "r"(a));
}
__device__ __forceinline__ void mma16f(float* c, const uint32_t* a, const uint32_t* b) {
    asm volatile("mma.sync.aligned.m16n8k16.row.col.f32.f16.f16.f32 "
        "{%0,%1,%2,%3}, {%4,%5,%6,%7}, {%8,%9}, {%0,%1,%2,%3};"
        : "+f"(c[0]), "+f"(c[1]), "+f"(c[2]), "+f"(c[3])
        : "r"(a[0]), "r"(a[1]), "r"(a[2]), "r"(a[3]), "r"(b[0]), "r"(b[1]));
}
__device__ __forceinline__ void mma16h(uint32_t* c, const uint32_t* a, const uint32_t* b) {
    asm volatile("mma.sync.aligned.m16n8k16.row.col.f16.f16.f16.f16 "
        "{%0,%1}, {%2,%3,%4,%5}, {%6,%7}, {%0,%1};"
        : "+r"(c[0]), "+r"(c[1])
        : "r"(a[0]), "r"(a[1]), "r"(a[2]), "r"(a[3]), "r"(b[0]), "r"(b[1]));
}

// ===== fp16 split GEMM: C[128m x 128n], 512 threads, 16 warps (4x4), 32x32/warp =====
#define SPAD   80
#define PLANE  10240

template <int PASSES, int ACT, int OUTMODE, int GATHB>
__global__ void __launch_bounds__(512, 1)
k_gemm_h(const __half* __restrict__ Ah, const __half* __restrict__ Al,
         const __half* __restrict__ Bh, const __half* __restrict__ Bl,
         const int* __restrict__ bIdx, int idxB,
         void* __restrict__ C0v, void* __restrict__ C1v,
         int K, int ldc, size_t aB, size_t bB, size_t cB) {
    extern __shared__ char smem[];
    constexpr uint32_t OFFB = (PASSES == 3 ? 2u : 1u) * PLANE;
    constexpr uint32_t STG  = (PASSES == 3 ? 4u : 2u) * PLANE;

    const int tid = threadIdx.x, bz = blockIdx.z;
    const int m0 = blockIdx.y * 128, n0 = blockIdx.x * 128;
    Ah += bz * aB + (size_t)m0 * K;
    if (PASSES == 3) Al += bz * aB + (size_t)m0 * K;
    const uint32_t s0 = s2u(smem);

    const int lr = tid >> 2, lg = tid & 3;
    const size_t go = (size_t)lr * K + lg * 8;
    size_t bgo;
    if (GATHB) {
        int r0 = bIdx[(size_t)bz * idxB + n0 + lr];
        bgo = (size_t)r0 * K + lg * 8;
    } else {
        Bh += bz * bB + (size_t)n0 * K;
        if (PASSES == 3) Bl += bz * bB + (size_t)n0 * K;
        bgo = go;
    }
    const uint32_t so = (uint32_t)(lr * SPAD + lg * 16);

    const int lane = tid & 31, wid = tid >> 5;
    const int wm = (wid & 3) * 32, wn = (wid >> 2) * 32;
    const int l8 = lane & 7, mid = lane >> 3;
    uint32_t aoff[2][2], boff[2][2];
#pragma unroll
    for (int mt = 0; mt < 2; mt++)
#pragma unroll
        for (int ks = 0; ks < 2; ks++)
            aoff[mt][ks] = (uint32_t)((wm + mt * 16 + (mid & 1) * 8 + l8) * SPAD
                                      + ((mid >> 1) * 8 + ks * 16) * 2);
#pragma unroll
    for (int p = 0; p < 2; p++)
#pragma unroll
        for (int ks = 0; ks < 2; ks++)
            boff[p][ks] = (uint32_t)(OFFB + (wn + p * 16 + (mid >> 1) * 8 + l8) * SPAD
                                     + ((mid & 1) * 8 + ks * 16) * 2);

    float acc[2][4][4];
    uint32_t acx[2][4][2];
#pragma unroll
    for (int mt = 0; mt < 2; mt++)
#pragma unroll
        for (int nt = 0; nt < 4; nt++) {
#pragma unroll
            for (int e = 0; e < 4; e++) acc[mt][nt][e] = 0.f;
            acx[mt][nt][0] = 0u; acx[mt][nt][1] = 0u;
        }

    const int nc = K >> 5;

#define LOADSTG(c) do { \
    uint32_t sb_ = s0 + ((c) & 3) * STG; \
    size_t ko_ = (size_t)(c) * 32; \
    cpa16h(sb_ + so,        Ah + go + ko_); \
    cpa16h(sb_ + OFFB + so, Bh + bgo + ko_); \
    if (PASSES == 3) { \
        cpa16h(sb_ + PLANE + so,        Al + go + ko_); \
        cpa16h(sb_ + OFFB + PLANE + so, Bl + bgo + ko_); \
    } \
    cpacommit(); \
} while (0)

    LOADSTG(0); LOADSTG(1); LOADSTG(2);

    for (int c = 0; c < nc; c++) {
        cpawait2();
        __syncthreads();
        if (c + 3 < nc) LOADSTG(c + 3); else cpacommit();
        const uint32_t sb = s0 + (c & 3) * STG;
#pragma unroll
        for (int ks = 0; ks < 2; ks++) {
            uint32_t fa[2][4], fb[2][4];
#pragma unroll
            for (int mt = 0; mt < 2; mt++) ldsm4(fa[mt], sb + aoff[mt][ks]);
#pragma unroll
            for (int p = 0; p < 2; p++) ldsm4(fb[p], sb + boff[p][ks]);
#pragma unroll
            for (int mt = 0; mt < 2; mt++)
#pragma unroll
                for (int nt = 0; nt < 4; nt++)
                    mma16f(acc[mt][nt], fa[mt], &fb[nt >> 1][(nt & 1) * 2]);
            if (PASSES == 3) {
                uint32_t fal[2][4], fbl[2][4];
#pragma unroll
                for (int p = 0; p < 2; p++) ldsm4(fbl[p], sb + boff[p][ks] + PLANE);
#pragma unroll
                for (int mt = 0; mt < 2; mt++)
#pragma unroll
                    for (int nt = 0; nt < 4; nt++)
                        mma16h(acx[mt][nt], fa[mt], &fbl[nt >> 1][(nt & 1) * 2]);
#pragma unroll
                for (int mt = 0; mt < 2; mt++) ldsm4(fal[mt], sb + aoff[mt][ks] + PLANE);
#pragma unroll
                for (int mt = 0; mt < 2; mt++)
#pragma unroll
                    for (int nt = 0; nt < 4; nt++)
                        mma16h(acx[mt][nt], fal[mt], &fb[nt >> 1][(nt & 1) * 2]);
            }
        }
    }
#undef LOADSTG

    const int qr = lane >> 2, qk = lane & 3;
    float csum[4][2];
    if (OUTMODE == 2) {
#pragma unroll
        for (int nt = 0; nt < 4; nt++) { csum[nt][0] = 0.f; csum[nt][1] = 0.f; }
    }
#pragma unroll
    for (int mt = 0; mt < 2; mt++) {
#pragma unroll
        for (int nt = 0; nt < 4; nt++) {
            const int r = m0 + wm + mt * 16 + qr;
            const int cc = n0 + wn + nt * 8 + qk * 2;
            float v0, v1, v2, v3;
            if (PASSES == 3) {
                float2 x01 = __half22float2(*(__half2*)&acx[mt][nt][0]);
                float2 x23 = __half22float2(*(__half2*)&acx[mt][nt][1]);
                v0 = (acc[mt][nt][0] + x01.x) * INV_SCALE;
                v1 = (acc[mt][nt][1] + x01.y) * INV_SCALE;
                v2 = (acc[mt][nt][2] + x23.x) * INV_SCALE;
                v3 = (acc[mt][nt][3] + x23.y) * INV_SCALE;
            } else {
                v0 = acc[mt][nt][0] * INV_SCALE;
                v1 = acc[mt][nt][1] * INV_SCALE;
                v2 = acc[mt][nt][2] * INV_SCALE;
                v3 = acc[mt][nt][3] * INV_SCALE;
            }
            if (ACT) { v0 = gelu_f(v0); v1 = gelu_f(v1); v2 = gelu_f(v2); v3 = gelu_f(v3); }
            if (OUTMODE == 1) {
                __half* C0 = (__half*)C0v + bz * cB;
                __half* C1 = (__half*)C1v + bz * cB;
                __half h0, l0, h1, l1;
                split16(v0, h0, l0); split16(v1, h1, l1);
                *(__half2*)&C0[(size_t)r * ldc + cc] = __halves2half2(h0, h1);
                *(__half2*)&C1[(size_t)r * ldc + cc] = __halves2half2(l0, l1);
                split16(v2, h0, l0); split16(v3, h1, l1);
                *(__half2*)&C0[(size_t)(r + 8) * ldc + cc] = __halves2half2(h0, h1);
                *(__half2*)&C1[(size_t)(r + 8) * ldc + cc] = __halves2half2(l0, l1);
            } else if (OUTMODE == 2) {
                __half* C0 = (__half*)C0v + bz * cB;
                *(__half2*)&C0[(size_t)r * ldc + cc] =
                    __halves2half2(__float2half_rn(v0), __float2half_rn(v1));
                *(__half2*)&C0[(size_t)(r + 8) * ldc + cc] =
                    __halves2half2(__float2half_rn(v2), __float2half_rn(v3));
                csum[nt][0] += v0 + v2;
                csum[nt][1] += v1 + v3;
            } else {
                float* C0 = (float*)C0v + bz * cB;
                float2 w0 = {v0, v1}, w1 = {v2, v3};
                *(float2*)&C0[(size_t)r * ldc + cc] = w0;
                *(float2*)&C0[(size_t)(r + 8) * ldc + cc] = w1;
            }
        }
    }

    if (OUTMODE == 2) {
        float* sbuf = (float*)smem;
        __syncthreads();
#pragma unroll
        for (int nt = 0; nt < 4; nt++)
#pragma unroll
            for (int pr = 0; pr < 2; pr++) {
                float s = csum[nt][pr];
                s += __shfl_xor_sync(0xffffffffu, s, 4);
                s += __shfl_xor_sync(0xffffffffu, s, 8);
                s += __shfl_xor_sync(0xffffffffu, s, 16);
                if (qr == 0) sbuf[wid * 32 + nt * 8 + qk * 2 + pr] = s;
            }
        __syncthreads();
        if (tid < 128) {
            int g = tid >> 5, c32 = tid & 31;
            float tot = sbuf[(g * 4 + 0) * 32 + c32] + sbuf[(g * 4 + 1) * 32 + c32]
                      + sbuf[(g * 4 + 2) * 32 + c32] + sbuf[(g * 4 + 3) * 32 + c32];
            g_scorep[((size_t)bz * 16 + blockIdx.y) * NPROC + n0 + tid] = tot;
        }
    }
}

// ---------------- main branch: gcmax + zero input rank ----------------
__global__ void k_gcmax(const float* __restrict__ x) {
    int bx = blockIdx.x;   // 16
    int zi = (bx * 256 + threadIdx.x) * 8;
#pragma unroll
    for (int q = 0; q < 8; q++) g_rank[zi + q] = 0;
    int b = bx >> 2, d = (bx & 3) * 256 + threadIdx.x;
    const float* p = x + (size_t)b * SS * DD + d;
    float m = -3.4e38f;
    for (int s = 0; s < SS; s++) m = fmaxf(m, p[(size_t)s * DD]);
    g_gc[b * DD + d] = m;
}

// ---------------- side branch: split(x) + split(IP) ----------------
__global__ void k_splitxip(const float* __restrict__ x, const float* __restrict__ IP) {
    size_t bid = blockIdx.x;
    if (bid < 8192) {
        size_t i = bid * 256 + threadIdx.x;       // float4 over BB*SS*DD/4
        float4 v = ((const float4*)x)[i];
        __half hx, lx, hy, ly, hz, lz, hw, lw;
        split16(v.x, hx, lx); split16(v.y, hy, ly);
        split16(v.z, hz, lz); split16(v.w, hw, lw);
        ((__half2*)g_xh)[2 * i]     = __halves2half2(hx, hy);
        ((__half2*)g_xh)[2 * i + 1] = __halves2half2(hz, hw);
        ((__half2*)g_xl)[2 * i]     = __halves2half2(lx, ly);
        ((__half2*)g_xl)[2 * i + 1] = __halves2half2(lz, lw);
    } else {
        size_t i = (bid - 8192) * 256 + threadIdx.x;   // float4 over NIN*DD/4
        float4 v = ((const float4*)IP)[i];
        __half hx, lx, hy, ly, hz, lz, hw, lw;
        split16(v.x * SCALE_B, hx, lx); split16(v.y * SCALE_B, hy, ly);
        split16(v.z * SCALE_B, hz, lz); split16(v.w * SCALE_B, hw, lw);
        ((__half2*)g_iph)[2 * i]     = __halves2half2(hx, hy);
        ((__half2*)g_iph)[2 * i + 1] = __halves2half2(hz, hw);
        ((__half2*)g_ipl)[2 * i]     = __halves2half2(lx, ly);
        ((__half2*)g_ipl)[2 * i + 1] = __halves2half2(lz, lw);
    }
}

// ---------------- router MLP + logits slice ----------------
__global__ void k_mlp_logits(const float* __restrict__ W1, const float* __restrict__ b1,
                             const float* __restrict__ lng, const float* __restrict__ lnb,
                             const float* __restrict__ W2, const float* __restrict__ b2,
                             const float* __restrict__ NK) {
    const int b = blockIdx.y;
    const int nb0 = blockIdx.x * (NIN / 16);
    __shared__ float sin[DD];
    __shared__ float sh[HH];
    __shared__ float sq[DR];
    __shared__ float red[8];
    __shared__ float smu, svar;
    const int tid = threadIdx.x, wid = tid >> 5, lane = tid & 31;

    for (int d = tid; d < DD; d += 256) sin[d] = g_gc[b * DD + d];
    __syncthreads();

    for (int o = wid; o < HH; o += 8) {
        float s = 0.f;
        for (int d = lane; d < DD; d += 32) s = fmaf(W1[(size_t)o * DD + d], sin[d], s);
#pragma unroll
        for (int off = 16; off; off >>= 1) s += __shfl_xor_sync(0xffffffffu, s, off);
        if (lane == 0) sh[o] = gelu_f(s + b1[o]);
    }
    __syncthreads();

    float v0 = sh[tid], v1 = sh[tid + 256];
    float s = v0 + v1;
#pragma unroll
    for (int off = 16; off; off >>= 1) s += __shfl_xor_sync(0xffffffffu, s, off);
    if (lane == 0) red[wid] = s;
    __syncthreads();
    if (tid == 0) { float t = 0.f; for (int w = 0; w < 8; w++) t += red[w]; smu = t / HH; }
    __syncthreads();
    float mu = smu;
    float d0 = v0 - mu, d1 = v1 - mu;
    float s2 = d0 * d0 + d1 * d1;
#pragma unroll
    for (int off = 16; off; off >>= 1) s2 += __shfl_xor_sync(0xffffffffu, s2, off);
    __syncthreads();
    if (lane == 0) red[wid] = s2;
    __syncthreads();
    if (tid == 0) { float t = 0.f; for (int w = 0; w < 8; w++) t += red[w]; svar = t / HH; }
    __syncthreads();
    float rstd = rsqrtf(svar + 1e-5f);
    sh[tid]       = d0 * rstd * lng[tid] + lnb[tid];
    sh[tid + 256] = d1 * rstd * lng[tid + 256] + lnb[tid + 256];
    __syncthreads();

    for (int o = wid; o < DR; o += 8) {
        float q = 0.f;
        for (int d = lane; d < HH; d += 32) q = fmaf(W2[(size_t)o * HH + d], sh[d], q);
#pragma unroll
        for (int off = 16; off; off >>= 1) q += __shfl_xor_sync(0xffffffffu, q, off);
        if (lane == 0) sq[o] = q + b2[o];
    }
    __syncthreads();

    for (int o = wid; o < NIN / 16; o += 8) {
        int oo = nb0 + o;
        float lg = 0.f;
        for (int d = lane; d < DR; d += 32) lg = fmaf(NK[(size_t)oo * DR + d], sq[d], lg);
#pragma unroll
        for (int off = 16; off; off >>= 1) lg += __shfl_xor_sync(0xffffffffu, lg, off);
        if (lane == 0) g_logits[(size_t)b * NIN + oo] = lg * 0.0625f;
    }
}

// ---------------- partial rank counting (sliced 8x, int atomics) ----------------
__global__ void k_selrank(const float* __restrict__ vals, int n, int* __restrict__ rank) {
    int b = blockIdx.z;
    const float* v = vals + (size_t)b * n;
    int i = blockIdx.x * 256 + threadIdx.x;
    float vi = v[i];
    int t0beg = blockIdx.y * (n >> 3);
    int t0end = t0beg + (n >> 3);
    __shared__ float sv[256];
    int r = 0;
    for (int t0 = t0beg; t0 < t0end; t0 += 256) {
        sv[threadIdx.x] = v[t0 + threadIdx.x];
        __syncthreads();
#pragma unroll 8
        for (int t = 0; t < 256; t++) {
            float vj = sv[t];
            int j = t0 + t;
            r += (vj > vi) || (vj == vi && j < i);
        }
        __syncthreads();
    }
    atomicAdd(&rank[(size_t)b * n + i], r);
}

// ---------------- compact: rank<k -> ascending index list ----------------
__global__ void k_compact(const int* __restrict__ rank, int n, int k, int* __restrict__ outp) {
    int b = blockIdx.x;
    const int* rk = rank + (size_t)b * n;
    int* op = outp + (size_t)b * k;
    __shared__ int warpCnt[32];
    __shared__ int sbase;
    int tid = threadIdx.x, lane = tid & 31, wid = tid >> 5;
    if (tid == 0) sbase = 0;
    __syncthreads();
    for (int c0 = 0; c0 < n; c0 += 1024) {
        int i = c0 + tid;
        int f = (rk[i] < k) ? 1 : 0;
        unsigned bal = __ballot_sync(0xffffffffu, f);
        if (lane == 0) warpCnt[wid] = __popc(bal);
        __syncthreads();
        int prefix = sbase;
        for (int w = 0; w < wid; w++) prefix += warpCnt[w];
        prefix += __popc(bal & ((1u << lane) - 1));
        if (f) op[prefix] = i;
        __syncthreads();
        if (tid == 0) { int t = 0; for (int w = 0; w < 32; w++) t += warpCnt[w]; sbase += t; }
        __syncthreads();
    }
}

// ---------------- gather PW columns + scale + split (512 thr) ----------
__global__ void k_gatherW(const float* __restrict__ PW) {
    int b = blockIdx.z;
    int k0 = blockIdx.x * 512;
    int p0 = blockIdx.y * 32;
    __shared__ int si[512];
    si[threadIdx.x] = g_iidx2[(size_t)b * KIN + k0 + threadIdx.x];
    __syncthreads();
    int col = si[threadIdx.x];
#pragma unroll 4
    for (int pp = 0; pp < 32; pp++) {
        int p = p0 + pp;
        float v = PW[(size_t)p * NIN + col] * SCALE_B;
        __half h, l;
        split16(v, h, l);
        size_t o = ((size_t)b * NPROC + p) * KIN + k0 + threadIdx.x;
        g_wgh[o] = h;
        g_wgl[o] = l;
    }
}

// ---------------- reduce 16 score partials -> scores; zero proc rank ----------
__global__ void k_scores2() {
    int b = blockIdx.y;
    int p = blockIdx.x * 256 + threadIdx.x;
    float s = 0.f;
#pragma unroll
    for (int t = 0; t < 16; t++) s += g_scorep[((size_t)b * 16 + t) * NPROC + p];
    g_scores[b * NPROC + p] = s * (1.0f / SS);
    g_rank[(size_t)b * NPROC + p] = 0;
}

// ---------------- fused: gathersp + po_t ----------
__global__ void k_gsp_pot(const float* __restrict__ PO) {
    int bid = blockIdx.x;
    if (bid < 65536) {
        int kx = (bid & 7) * 256 + threadIdx.x;
        int s = (bid >> 3) & 2047;
        int b = bid >> 14;
        int pi = g_pidx2[(size_t)b * KPROC + kx];
        g_sph[((size_t)b * SS + s) * KPROC + kx] =
            g_proch[((size_t)b * SS + s) * NPROC + pi];
    } else {
        __shared__ float t[32][33];
        int id = bid - 65536;
        int k0 = (id & 63) * 32;
        int d0 = ((id >> 6) & 31) * 32;
        int b = id >> 11;
        int tx = threadIdx.x & 31, ty = threadIdx.x >> 5;
        for (int i = ty; i < 32; i += 8) {
            int pi = g_pidx2[(size_t)b * KPROC + k0 + i];
            t[i][tx] = PO[(size_t)pi * DD + d0 + tx];
        }
        __syncthreads();
        for (int i = ty; i < 32; i += 8)
            g_poth[((size_t)b * DD + d0 + i) * KPROC + k0 + tx] =
                __float2half_rn(t[tx][i] * SCALE_B);
    }
}

// ---------------- host side ----------------
extern "C" void kernel_launch(void* const* d_in, const int* in_sizes, int n_in,
                              void* d_out, int out_size) {
    const float* x   = (const float*)d_in[0];
    const float* W1  = (const float*)d_in[1];
    const float* b1  = (const float*)d_in[2];
    const float* lng = (const float*)d_in[3];
    const float* lnb = (const float*)d_in[4];
    const float* W2  = (const float*)d_in[5];
    const float* b2  = (const float*)d_in[6];
    const float* NK  = (const float*)d_in[7];
    const float* IP  = (const float*)d_in[8];
    const float* PW  = (const float*)d_in[9];
    const float* PO  = (const float*)d_in[10];
    float* out = (float*)d_out;

    void *p_logits, *p_rank, *p_iidx2, *p_pidx2, *p_scores;
    void *p_xh, *p_xl, *p_iph, *p_ipl, *p_selh, *p_sell, *p_wgh, *p_wgl;
    void *p_proch, *p_sph, *p_poth;
    cudaGetSymbolAddress(&p_logits, g_logits);
    cudaGetSymbolAddress(&p_rank, g_rank);
    cudaGetSymbolAddress(&p_iidx2, g_iidx2);
    cudaGetSymbolAddress(&p_pidx2, g_pidx2);
    cudaGetSymbolAddress(&p_scores, g_scores);
    cudaGetSymbolAddress(&p_xh, g_xh);
    cudaGetSymbolAddress(&p_xl, g_xl);
    cudaGetSymbolAddress(&p_iph, g_iph);
    cudaGetSymbolAddress(&p_ipl, g_ipl);
    cudaGetSymbolAddress(&p_selh, g_selh);
    cudaGetSymbolAddress(&p_sell, g_sell);
    cudaGetSymbolAddress(&p_wgh, g_wgh);
    cudaGetSymbolAddress(&p_wgl, g_wgl);
    cudaGetSymbolAddress(&p_proch, g_proch);
    cudaGetSymbolAddress(&p_sph, g_sph);
    cudaGetSymbolAddress(&p_poth, g_poth);

    const int SM3 = 4 * 4 * PLANE;
    const int SM1 = 4 * 2 * PLANE;
    cudaFuncSetAttribute((const void*)&k_gemm_h<3, 1, 1, 1>, cudaFuncAttributeMaxDynamicSharedMemorySize, SM3);
    cudaFuncSetAttribute((const void*)&k_gemm_h<3, 1, 2, 0>, cudaFuncAttributeMaxDynamicSharedMemorySize, SM3);
    cudaFuncSetAttribute((const void*)&k_gemm_h<1, 0, 0, 0>, cudaFuncAttributeMaxDynamicSharedMemorySize, SM1);

    // side stream + fork/join events (created once; no device memory)
    static cudaStream_t s2 = nullptr;
    static cudaEvent_t evF1, evJ1, evF2, evJ2;
    if (!s2) {
        cudaStreamCreateWithFlags(&s2, cudaStreamNonBlocking);
        cudaEventCreateWithFlags(&evF1, cudaEventDisableTiming);
        cudaEventCreateWithFlags(&evJ1, cudaEventDisableTiming);
        cudaEventCreateWithFlags(&evF2, cudaEventDisableTiming);
        cudaEventCreateWithFlags(&evJ2, cudaEventDisableTiming);
    }

    // ---- fork 1: splits on s2, router chain on main ----
    cudaEventRecord(evF1, 0);
    cudaStreamWaitEvent(s2, evF1, 0);
    k_splitxip<<<16384, 256, 0, s2>>>(x, IP);

    k_gcmax<<<16, 256>>>(x);
    k_mlp_logits<<<dim3(16, BB), 256>>>(W1, b1, lng, lnb, W2, b2, NK);
    k_selrank<<<dim3(NIN / 256, 8, BB), 256>>>((const float*)p_logits, NIN, (int*)p_rank);
    k_compact<<<BB, 1024>>>((const int*)p_rank, NIN, KIN, (int*)p_iidx2);

    cudaEventRecord(evJ1, s2);
    cudaStreamWaitEvent(0, evJ1, 0);

    // ---- fork 2: gatherW on s2 overlapping sel GEMM on main ----
    cudaEventRecord(evF2, 0);
    cudaStreamWaitEvent(s2, evF2, 0);
    k_gatherW<<<dim3(KIN / 512, NPROC / 32, BB), 512, 0, s2>>>(PW);

    k_gemm_h<3, 1, 1, 1><<<dim3(KIN / 128, SS / 128, BB), 512, SM3>>>(
        (const __half*)p_xh, (const __half*)p_xl, (const __half*)p_iph, (const __half*)p_ipl,
        (const int*)p_iidx2, KIN, p_selh, p_sell, DD, KIN,
        (size_t)SS * DD, 0, (size_t)SS * KIN);

    cudaEventRecord(evJ2, s2);
    cudaStreamWaitEvent(0, evJ2, 0);

    // ---- proc GEMM -> fp16 proc + score partials ----
    k_gemm_h<3, 1, 2, 0><<<dim3(NPROC / 128, SS / 128, BB), 512, SM3>>>(
        (const __half*)p_selh, (const __half*)p_sell, (const __half*)p_wgh, (const __half*)p_wgl,
        nullptr, 0, p_proch, nullptr, KIN, NPROC,
        (size_t)SS * KIN, (size_t)NPROC * KIN, (size_t)SS * NPROC);

    // ---- process selection ----
    k_scores2<<<dim3(NPROC / 256, BB), 256>>>();
    k_selrank<<<dim3(NPROC / 256, 8, BB), 256>>>((const float*)p_scores, NPROC, (int*)p_rank);
    k_compact<<<BB, 1024>>>((const int*)p_rank, NPROC, KPROC, (int*)p_pidx2);

    // ---- gathers for output GEMM ----
    k_gsp_pot<<<65536 + 8192, 256>>>(PO);

    // ---- out GEMM, 1-pass fp16 ----
    k_gemm_h<1, 0, 0, 0><<<dim3(DD / 128, SS / 128, BB), 512, SM1>>>(
        (const __half*)p_sph, (const __half*)p_sph, (const __half*)p_poth, (const __half*)p_poth,
        nullptr, 0, out, nullptr, KPROC, DD,
        (size_t)SS * KPROC, (size_t)DD * KPROC, (size_t)SS * DD);
}

// round 16
// speedup vs baseline: 1.1124x; 1.0234x over previous
#include <cuda_runtime.h>
#include <cuda_fp16.h>
#include <math.h>
#include <stdint.h>

#define BB     4
#define SS     2048
#define DD     1024
#define NIN    8192
#define NPROC  4096
#define DR     256
#define HH     512
#define KIN    4096
#define KPROC  2048

#define SCALE_B   4096.0f
#define INV_SCALE 2.44140625e-4f

// ---------------- scratch (static device memory; no allocs) ----------------
__device__ float g_gcp[16][BB * DD];        // per-S-slice partial max
__device__ float g_logits[BB * NIN];
__device__ int   g_rank[BB * NIN];
__device__ int   g_iidx2[BB * KIN];
__device__ int   g_pidx2[BB * KPROC];
__device__ float g_scores[BB * NPROC];
__device__ float g_scorep[16 * BB * NPROC];

__align__(16) __device__ __half g_xh[(size_t)BB * SS * DD];
__align__(16) __device__ __half g_xl[(size_t)BB * SS * DD];
__align__(16) __device__ __half g_iph[(size_t)NIN * DD];
__align__(16) __device__ __half g_ipl[(size_t)NIN * DD];
__align__(16) __device__ __half g_selh[(size_t)BB * SS * KIN];
__align__(16) __device__ __half g_sell[(size_t)BB * SS * KIN];
__align__(16) __device__ __half g_wgh[(size_t)BB * NPROC * KIN];
__align__(16) __device__ __half g_wgl[(size_t)BB * NPROC * KIN];
__align__(16) __device__ __half g_sph[(size_t)BB * SS * KPROC];
__align__(16) __device__ __half g_poth[(size_t)BB * DD * KPROC];
__align__(16) __device__ __half g_proch[(size_t)BB * SS * NPROC];

__device__ __forceinline__ float gelu_f(float x) {
    return 0.5f * x * (1.0f + erff(x * 0.70710678118654752440f));
}
__device__ __forceinline__ void split16(float v, __half& h, __half& l) {
    h = __float2half_rn(v);
    l = __float2half_rn(v - __half2float(h));
}
__device__ __forceinline__ uint32_t fkey(float v) {
    uint32_t u = __float_as_uint(v);
    return u ^ ((uint32_t)(((int)u) >> 31) | 0x80000000u);
}

__device__ __forceinline__ uint32_t s2u(const void* p) {
    uint32_t a;
    asm("{ .reg .u64 t; cvta.to.shared.u64 t, %1; cvt.u32.u64 %0, t; }" : "=r"(a) : "l"(p));
    return a;
}
__device__ __forceinline__ void cpa16h(uint32_t dst, const __half* src) {
    asm volatile("cp.async.cg.shared.global [%0], [%1], 16;" :: "r"(dst), "l"(src));
}
__device__ __forceinline__ void cpacommit() { asm volatile("cp.async.commit_group;" ::: "memory"); }
__device__ __forceinline__ void cpawait2()  { asm volatile("cp.async.wait_group 2;" ::: "memory"); }

__device__ __forceinline__ void ldsm4(uint32_t* r, uint32_t a) {
    asm volatile("ldmatrix.sync.aligned.m8n8.x4.shared.b16 {%0,%1,%2,%3}, [%4];"
        : "=r"(r[0]), "=r"(r[1]), "=r"(r[2]), "=r"(r[3]) : "r"(a));
}
__device__ __forceinline__ void mma16f(float* c, const uint32_t* a, const uint32_t* b) {
    asm volatile("mma.sync.aligned.m16n8k16.row.col.f32.f16.f16.f32 "
        "{%0,%1,%2,%3}, {%4,%5,%6,%7}, {%8,%9}, {%0,%1,%2,%3};"
        : "+f"(c[0]), "+f"(c[1]), "+f"(c[2]), "+f"(c[3])
        : "r"(a[0]), "r"(a[1]), "r"(a[2]), "r"(a[3]), "r"(b[0]), "r"(b[1]));
}
__device__ __forceinline__ void mma16h(uint32_t* c, const uint32_t* a, const uint32_t* b) {
    asm volatile("mma.sync.aligned.m16n8k16.row.col.f16.f16.f16.f16 "
        "{%0,%1}, {%2,%3,%4,%5}, {%6,%7}, {%0,%1};"
        : "+r"(c[0]), "+r"(c[1])
        : "r"(a[0]), "r"(a[1]), "r"(a[2]), "r"(a[3]), "r"(b[0]), "r"(b[1]));
}

// ===== fp16 split GEMM: C[128m x 128n], 512 threads, 16 warps (4x4), 32x32/warp =====
#define SPAD   80
#define PLANE  10240

template <int PASSES, int ACT, int OUTMODE, int GATHB>
__global__ void __launch_bounds__(512, 1)
k_gemm_h(const __half* __restrict__ Ah, const __half* __restrict__ Al,
         const __half* __restrict__ Bh, const __half* __restrict__ Bl,
         const int* __restrict__ bIdx, int idxB,
         void* __restrict__ C0v, void* __restrict__ C1v,
         int K, int ldc, size_t aB, size_t bB, size_t cB) {
    extern __shared__ char smem[];
    constexpr uint32_t OFFB = (PASSES == 3 ? 2u : 1u) * PLANE;
    constexpr uint32_t STG  = (PASSES == 3 ? 4u : 2u) * PLANE;

    const int tid = threadIdx.x, bz = blockIdx.z;
    const int m0 = blockIdx.y * 128, n0 = blockIdx.x * 128;
    Ah += bz * aB + (size_t)m0 * K;
    if (PASSES == 3) Al += bz * aB + (size_t)m0 * K;
    const uint32_t s0 = s2u(smem);

    const int lr = tid >> 2, lg = tid & 3;
    const size_t go = (size_t)lr * K + lg * 8;
    size_t bgo;
    if (GATHB) {
        int r0 = bIdx[(size_t)bz * idxB + n0 + lr];
        bgo = (size_t)r0 * K + lg * 8;
    } else {
        Bh += bz * bB + (size_t)n0 * K;
        if (PASSES == 3) Bl += bz * bB + (size_t)n0 * K;
        bgo = go;
    }
    const uint32_t so = (uint32_t)(lr * SPAD + lg * 16);

    const int lane = tid & 31, wid = tid >> 5;
    const int wm = (wid & 3) * 32, wn = (wid >> 2) * 32;
    const int l8 = lane & 7, mid = lane >> 3;
    uint32_t aoff[2][2], boff[2][2];
#pragma unroll
    for (int mt = 0; mt < 2; mt++)
#pragma unroll
        for (int ks = 0; ks < 2; ks++)
            aoff[mt][ks] = (uint32_t)((wm + mt * 16 + (mid & 1) * 8 + l8) * SPAD
                                      + ((mid >> 1) * 8 + ks * 16) * 2);
#pragma unroll
    for (int p = 0; p < 2; p++)
#pragma unroll
        for (int ks = 0; ks < 2; ks++)
            boff[p][ks] = (uint32_t)(OFFB + (wn + p * 16 + (mid >> 1) * 8 + l8) * SPAD
                                     + ((mid & 1) * 8 + ks * 16) * 2);

    float acc[2][4][4];
    uint32_t acx[2][4][2];
#pragma unroll
    for (int mt = 0; mt < 2; mt++)
#pragma unroll
        for (int nt = 0; nt < 4; nt++) {
#pragma unroll
            for (int e = 0; e < 4; e++) acc[mt][nt][e] = 0.f;
            acx[mt][nt][0] = 0u; acx[mt][nt][1] = 0u;
        }

    const int nc = K >> 5;

#define LOADSTG(c) do { \
    uint32_t sb_ = s0 + ((c) & 3) * STG; \
    size_t ko_ = (size_t)(c) * 32; \
    cpa16h(sb_ + so,        Ah + go + ko_); \
    cpa16h(sb_ + OFFB + so, Bh + bgo + ko_); \
    if (PASSES == 3) { \
        cpa16h(sb_ + PLANE + so,        Al + go + ko_); \
        cpa16h(sb_ + OFFB + PLANE + so, Bl + bgo + ko_); \
    } \
    cpacommit(); \
} while (0)

    LOADSTG(0); LOADSTG(1); LOADSTG(2);

    for (int c = 0; c < nc; c++) {
        cpawait2();
        __syncthreads();
        if (c + 3 < nc) LOADSTG(c + 3); else cpacommit();
        const uint32_t sb = s0 + (c & 3) * STG;
#pragma unroll
        for (int ks = 0; ks < 2; ks++) {
            uint32_t fa[2][4], fb[2][4];
#pragma unroll
            for (int mt = 0; mt < 2; mt++) ldsm4(fa[mt], sb + aoff[mt][ks]);
#pragma unroll
            for (int p = 0; p < 2; p++) ldsm4(fb[p], sb + boff[p][ks]);
#pragma unroll
            for (int mt = 0; mt < 2; mt++)
#pragma unroll
                for (int nt = 0; nt < 4; nt++)
                    mma16f(acc[mt][nt], fa[mt], &fb[nt >> 1][(nt & 1) * 2]);
            if (PASSES == 3) {
                uint32_t fal[2][4], fbl[2][4];
#pragma unroll
                for (int p = 0; p < 2; p++) ldsm4(fbl[p], sb + boff[p][ks] + PLANE);
#pragma unroll
                for (int mt = 0; mt < 2; mt++)
#pragma unroll
                    for (int nt = 0; nt < 4; nt++)
                        mma16h(acx[mt][nt], fa[mt], &fbl[nt >> 1][(nt & 1) * 2]);
#pragma unroll
                for (int mt = 0; mt < 2; mt++) ldsm4(fal[mt], sb + aoff[mt][ks] + PLANE);
#pragma unroll
                for (int mt = 0; mt < 2; mt++)
#pragma unroll
                    for (int nt = 0; nt < 4; nt++)
                        mma16h(acx[mt][nt], fal[mt], &fb[nt >> 1][(nt & 1) * 2]);
            }
        }
    }
#undef LOADSTG

    const int qr = lane >> 2, qk = lane & 3;
    float csum[4][2];
    if (OUTMODE == 2) {
#pragma unroll
        for (int nt = 0; nt < 4; nt++) { csum[nt][0] = 0.f; csum[nt][1] = 0.f; }
    }
#pragma unroll
    for (int mt = 0; mt < 2; mt++) {
#pragma unroll
        for (int nt = 0; nt < 4; nt++) {
            const int r = m0 + wm + mt * 16 + qr;
            const int cc = n0 + wn + nt * 8 + qk * 2;
            float v0, v1, v2, v3;
            if (PASSES == 3) {
                float2 x01 = __half22float2(*(__half2*)&acx[mt][nt][0]);
                float2 x23 = __half22float2(*(__half2*)&acx[mt][nt][1]);
                v0 = (acc[mt][nt][0] + x01.x) * INV_SCALE;
                v1 = (acc[mt][nt][1] + x01.y) * INV_SCALE;
                v2 = (acc[mt][nt][2] + x23.x) * INV_SCALE;
                v3 = (acc[mt][nt][3] + x23.y) * INV_SCALE;
            } else {
                v0 = acc[mt][nt][0] * INV_SCALE;
                v1 = acc[mt][nt][1] * INV_SCALE;
                v2 = acc[mt][nt][2] * INV_SCALE;
                v3 = acc[mt][nt][3] * INV_SCALE;
            }
            if (ACT) { v0 = gelu_f(v0); v1 = gelu_f(v1); v2 = gelu_f(v2); v3 = gelu_f(v3); }
            if (OUTMODE == 1) {
                __half* C0 = (__half*)C0v + bz * cB;
                __half* C1 = (__half*)C1v + bz * cB;
                __half h0, l0, h1, l1;
                split16(v0, h0, l0); split16(v1, h1, l1);
                *(__half2*)&C0[(size_t)r * ldc + cc] = __halves2half2(h0, h1);
                *(__half2*)&C1[(size_t)r * ldc + cc] = __halves2half2(l0, l1);
                split16(v2, h0, l0); split16(v3, h1, l1);
                *(__half2*)&C0[(size_t)(r + 8) * ldc + cc] = __halves2half2(h0, h1);
                *(__half2*)&C1[(size_t)(r + 8) * ldc + cc] = __halves2half2(l0, l1);
            } else if (OUTMODE == 2) {
                __half* C0 = (__half*)C0v + bz * cB;
                *(__half2*)&C0[(size_t)r * ldc + cc] =
                    __halves2half2(__float2half_rn(v0), __float2half_rn(v1));
                *(__half2*)&C0[(size_t)(r + 8) * ldc + cc] =
                    __halves2half2(__float2half_rn(v2), __float2half_rn(v3));
                csum[nt][0] += v0 + v2;
                csum[nt][1] += v1 + v3;
            } else {
                float* C0 = (float*)C0v + bz * cB;
                float2 w0 = {v0, v1}, w1 = {v2, v3};
                *(float2*)&C0[(size_t)r * ldc + cc] = w0;
                *(float2*)&C0[(size_t)(r + 8) * ldc + cc] = w1;
            }
        }
    }

    if (OUTMODE == 2) {
        float* sbuf = (float*)smem;
        __syncthreads();
#pragma unroll
        for (int nt = 0; nt < 4; nt++)
#pragma unroll
            for (int pr = 0; pr < 2; pr++) {
                float s = csum[nt][pr];
                s += __shfl_xor_sync(0xffffffffu, s, 4);
                s += __shfl_xor_sync(0xffffffffu, s, 8);
                s += __shfl_xor_sync(0xffffffffu, s, 16);
                if (qr == 0) sbuf[wid * 32 + nt * 8 + qk * 2 + pr] = s;
            }
        __syncthreads();
        if (tid < 128) {
            int g = tid >> 5, c32 = tid & 31;
            float tot = sbuf[(g * 4 + 0) * 32 + c32] + sbuf[(g * 4 + 1) * 32 + c32]
                      + sbuf[(g * 4 + 2) * 32 + c32] + sbuf[(g * 4 + 3) * 32 + c32];
            g_scorep[((size_t)bz * 16 + blockIdx.y) * NPROC + n0 + tid] = tot;
        }
    }
}

// ---------------- gcmax phase 1: per-S-slice partial max + zero rank ------------
__global__ void k_gcmax(const float* __restrict__ x) {
    int sy = blockIdx.y;
    int bx = blockIdx.x;
    if (sy == 0) {
        int zi = (bx * 256 + threadIdx.x) * 8;
#pragma unroll
        for (int q = 0; q < 8; q++) g_rank[zi + q] = 0;
    }
    int b = bx >> 2, d = (bx & 3) * 256 + threadIdx.x;
    const float* p = x + (size_t)b * SS * DD + (size_t)sy * 128 * DD + d;
    float m = -3.4e38f;
    for (int s = 0; s < 128; s++) m = fmaxf(m, p[(size_t)s * DD]);
    g_gcp[sy][b * DD + d] = m;
}

// ---------------- side branch: split(x) + split(IP) ----------------
__global__ void k_splitxip(const float* __restrict__ x, const float* __restrict__ IP) {
    size_t bid = blockIdx.x;
    if (bid < 8192) {
        size_t i = bid * 256 + threadIdx.x;
        float4 v = ((const float4*)x)[i];
        __half hx, lx, hy, ly, hz, lz, hw, lw;
        split16(v.x, hx, lx); split16(v.y, hy, ly);
        split16(v.z, hz, lz); split16(v.w, hw, lw);
        ((__half2*)g_xh)[2 * i]     = __halves2half2(hx, hy);
        ((__half2*)g_xh)[2 * i + 1] = __halves2half2(hz, hw);
        ((__half2*)g_xl)[2 * i]     = __halves2half2(lx, ly);
        ((__half2*)g_xl)[2 * i + 1] = __halves2half2(lz, lw);
    } else {
        size_t i = (bid - 8192) * 256 + threadIdx.x;
        float4 v = ((const float4*)IP)[i];
        __half hx, lx, hy, ly, hz, lz, hw, lw;
        split16(v.x * SCALE_B, hx, lx); split16(v.y * SCALE_B, hy, ly);
        split16(v.z * SCALE_B, hz, lz); split16(v.w * SCALE_B, hw, lw);
        ((__half2*)g_iph)[2 * i]     = __halves2half2(hx, hy);
        ((__half2*)g_iph)[2 * i + 1] = __halves2half2(hz, hw);
        ((__half2*)g_ipl)[2 * i]     = __halves2half2(lx, ly);
        ((__half2*)g_ipl)[2 * i + 1] = __halves2half2(lz, lw);
    }
}

// ---------------- router MLP + logits slice (reduces gc partials) ----------------
__global__ void k_mlp_logits(const float* __restrict__ W1, const float* __restrict__ b1,
                             const float* __restrict__ lng, const float* __restrict__ lnb,
                             const float* __restrict__ W2, const float* __restrict__ b2,
                             const float* __restrict__ NK) {
    const int b = blockIdx.y;
    const int nb0 = blockIdx.x * (NIN / 16);
    __shared__ float sin[DD];
    __shared__ float sh[HH];
    __shared__ float sq[DR];
    __shared__ float red[8];
    __shared__ float smu, svar;
    const int tid = threadIdx.x, wid = tid >> 5, lane = tid & 31;

    for (int d = tid; d < DD; d += 256) {
        float m = -3.4e38f;
#pragma unroll
        for (int t = 0; t < 16; t++) m = fmaxf(m, g_gcp[t][b * DD + d]);
        sin[d] = m;
    }
    __syncthreads();

    for (int o = wid; o < HH; o += 8) {
        float s = 0.f;
        for (int d = lane; d < DD; d += 32) s = fmaf(W1[(size_t)o * DD + d], sin[d], s);
#pragma unroll
        for (int off = 16; off; off >>= 1) s += __shfl_xor_sync(0xffffffffu, s, off);
        if (lane == 0) sh[o] = gelu_f(s + b1[o]);
    }
    __syncthreads();

    float v0 = sh[tid], v1 = sh[tid + 256];
    float s = v0 + v1;
#pragma unroll
    for (int off = 16; off; off >>= 1) s += __shfl_xor_sync(0xffffffffu, s, off);
    if (lane == 0) red[wid] = s;
    __syncthreads();
    if (tid == 0) { float t = 0.f; for (int w = 0; w < 8; w++) t += red[w]; smu = t / HH; }
    __syncthreads();
    float mu = smu;
    float d0 = v0 - mu, d1 = v1 - mu;
    float s2 = d0 * d0 + d1 * d1;
#pragma unroll
    for (int off = 16; off; off >>= 1) s2 += __shfl_xor_sync(0xffffffffu, s2, off);
    __syncthreads();
    if (lane == 0) red[wid] = s2;
    __syncthreads();
    if (tid == 0) { float t = 0.f; for (int w = 0; w < 8; w++) t += red[w]; svar = t / HH; }
    __syncthreads();
    float rstd = rsqrtf(svar + 1e-5f);
    sh[tid]       = d0 * rstd * lng[tid] + lnb[tid];
    sh[tid + 256] = d1 * rstd * lng[tid + 256] + lnb[tid + 256];
    __syncthreads();

    for (int o = wid; o < DR; o += 8) {
        float q = 0.f;
        for (int d = lane; d < HH; d += 32) q = fmaf(W2[(size_t)o * HH + d], sh[d], q);
#pragma unroll
        for (int off = 16; off; off >>= 1) q += __shfl_xor_sync(0xffffffffu, q, off);
        if (lane == 0) sq[o] = q + b2[o];
    }
    __syncthreads();

    for (int o = wid; o < NIN / 16; o += 8) {
        int oo = nb0 + o;
        float lg = 0.f;
        for (int d = lane; d < DR; d += 32) lg = fmaf(NK[(size_t)oo * DR + d], sq[d], lg);
#pragma unroll
        for (int off = 16; off; off >>= 1) lg += __shfl_xor_sync(0xffffffffu, lg, off);
        if (lane == 0) g_logits[(size_t)b * NIN + oo] = lg * 0.0625f;
    }
}

// ---------------- partial rank counting, u64 keys (exact lax.top_k semantics) ----
__global__ void k_selrank(const float* __restrict__ vals, int n, int* __restrict__ rank) {
    int b = blockIdx.z;
    const float* v = vals + (size_t)b * n;
    int i = blockIdx.x * 256 + threadIdx.x;
    unsigned long long ki = ((unsigned long long)fkey(v[i]) << 32) | (uint32_t)(n - 1 - i);
    int t0beg = blockIdx.y * (n >> 3);
    int t0end = t0beg + (n >> 3);
    __shared__ unsigned long long sv[256];
    int r = 0;
    for (int t0 = t0beg; t0 < t0end; t0 += 256) {
        int j = t0 + threadIdx.x;
        sv[threadIdx.x] = ((unsigned long long)fkey(v[j]) << 32) | (uint32_t)(n - 1 - j);
        __syncthreads();
#pragma unroll 8
        for (int t = 0; t < 256; t++) r += (sv[t] > ki);
        __syncthreads();
    }
    atomicAdd(&rank[(size_t)b * n + i], r);
}

// ---------------- compact: rank<k -> ascending index list ----------------
__global__ void k_compact(const int* __restrict__ rank, int n, int k, int* __restrict__ outp) {
    int b = blockIdx.x;
    const int* rk = rank + (size_t)b * n;
    int* op = outp + (size_t)b * k;
    __shared__ int warpCnt[32];
    __shared__ int sbase;
    int tid = threadIdx.x, lane = tid & 31, wid = tid >> 5;
    if (tid == 0) sbase = 0;
    __syncthreads();
    for (int c0 = 0; c0 < n; c0 += 1024) {
        int i = c0 + tid;
        int f = (rk[i] < k) ? 1 : 0;
        unsigned bal = __ballot_sync(0xffffffffu, f);
        if (lane == 0) warpCnt[wid] = __popc(bal);
        __syncthreads();
        int prefix = sbase;
        for (int w = 0; w < wid; w++) prefix += warpCnt[w];
        prefix += __popc(bal & ((1u << lane) - 1));
        if (f) op[prefix] = i;
        __syncthreads();
        if (tid == 0) { int t = 0; for (int w = 0; w < 32; w++) t += warpCnt[w]; sbase += t; }
        __syncthreads();
    }
}

// ---------------- gather PW columns + scale + split (512 thr) ----------
__global__ void k_gatherW(const float* __restrict__ PW) {
    int b = blockIdx.z;
    int k0 = blockIdx.x * 512;
    int p0 = blockIdx.y * 32;
    __shared__ int si[512];
    si[threadIdx.x] = g_iidx2[(size_t)b * KIN + k0 + threadIdx.x];
    __syncthreads();
    int col = si[threadIdx.x];
#pragma unroll 4
    for (int pp = 0; pp < 32; pp++) {
        int p = p0 + pp;
        float v = PW[(size_t)p * NIN + col] * SCALE_B;
        __half h, l;
        split16(v, h, l);
        size_t o = ((size_t)b * NPROC + p) * KIN + k0 + threadIdx.x;
        g_wgh[o] = h;
        g_wgl[o] = l;
    }
}

// ---------------- reduce 16 score partials -> scores; zero proc rank ----------
__global__ void k_scores2() {
    int b = blockIdx.y;
    int p = blockIdx.x * 256 + threadIdx.x;
    float s = 0.f;
#pragma unroll
    for (int t = 0; t < 16; t++) s += g_scorep[((size_t)b * 16 + t) * NPROC + p];
    g_scores[b * NPROC + p] = s * (1.0f / SS);
    g_rank[(size_t)b * NPROC + p] = 0;
}

// ---------------- fused gathersp + po_t for a 2-batch range ----------
__global__ void k_gsp_pot(const float* __restrict__ PO, int b0) {
    int bid = blockIdx.x;
    if (bid < 32768) {
        int kx = (bid & 7) * 256 + threadIdx.x;
        int s = (bid >> 3) & 2047;
        int b = b0 + (bid >> 14);
        int pi = g_pidx2[(size_t)b * KPROC + kx];
        g_sph[((size_t)b * SS + s) * KPROC + kx] =
            g_proch[((size_t)b * SS + s) * NPROC + pi];
    } else {
        __shared__ float t[32][33];
        int id = bid - 32768;
        int k0 = (id & 63) * 32;
        int d0 = ((id >> 6) & 31) * 32;
        int b = b0 + (id >> 11);
        int tx = threadIdx.x & 31, ty = threadIdx.x >> 5;
        for (int i = ty; i < 32; i += 8) {
            int pi = g_pidx2[(size_t)b * KPROC + k0 + i];
            t[i][tx] = PO[(size_t)pi * DD + d0 + tx];
        }
        __syncthreads();
        for (int i = ty; i < 32; i += 8)
            g_poth[((size_t)b * DD + d0 + i) * KPROC + k0 + tx] =
                __float2half_rn(t[tx][i] * SCALE_B);
    }
}

// ---------------- host side ----------------
extern "C" void kernel_launch(void* const* d_in, const int* in_sizes, int n_in,
                              void* d_out, int out_size) {
    const float* x   = (const float*)d_in[0];
    const float* W1  = (const float*)d_in[1];
    const float* b1  = (const float*)d_in[2];
    const float* lng = (const float*)d_in[3];
    const float* lnb = (const float*)d_in[4];
    const float* W2  = (const float*)d_in[5];
    const float* b2  = (const float*)d_in[6];
    const float* NK  = (const float*)d_in[7];
    const float* IP  = (const float*)d_in[8];
    const float* PW  = (const float*)d_in[9];
    const float* PO  = (const float*)d_in[10];
    float* out = (float*)d_out;

    void *p_logits, *p_rank, *p_iidx2, *p_pidx2, *p_scores;
    void *p_xh, *p_xl, *p_iph, *p_ipl, *p_selh, *p_sell, *p_wgh, *p_wgl;
    void *p_proch, *p_sph, *p_poth;
    cudaGetSymbolAddress(&p_logits, g_logits);
    cudaGetSymbolAddress(&p_rank, g_rank);
    cudaGetSymbolAddress(&p_iidx2, g_iidx2);
    cudaGetSymbolAddress(&p_pidx2, g_pidx2);
    cudaGetSymbolAddress(&p_scores, g_scores);
    cudaGetSymbolAddress(&p_xh, g_xh);
    cudaGetSymbolAddress(&p_xl, g_xl);
    cudaGetSymbolAddress(&p_iph, g_iph);
    cudaGetSymbolAddress(&p_ipl, g_ipl);
    cudaGetSymbolAddress(&p_selh, g_selh);
    cudaGetSymbolAddress(&p_sell, g_sell);
    cudaGetSymbolAddress(&p_wgh, g_wgh);
    cudaGetSymbolAddress(&p_wgl, g_wgl);
    cudaGetSymbolAddress(&p_proch, g_proch);
    cudaGetSymbolAddress(&p_sph, g_sph);
    cudaGetSymbolAddress(&p_poth, g_poth);

    const int SM3 = 4 * 4 * PLANE;
    const int SM1 = 4 * 2 * PLANE;
    cudaFuncSetAttribute((const void*)&k_gemm_h<3, 1, 1, 1>, cudaFuncAttributeMaxDynamicSharedMemorySize, SM3);
    cudaFuncSetAttribute((const void*)&k_gemm_h<3, 1, 2, 0>, cudaFuncAttributeMaxDynamicSharedMemorySize, SM3);
    cudaFuncSetAttribute((const void*)&k_gemm_h<1, 0, 0, 0>, cudaFuncAttributeMaxDynamicSharedMemorySize, SM1);

    static cudaStream_t s2 = nullptr;
    static cudaEvent_t evF1, evJ1, evF2, evJ2, evF3, evJ3;
    if (!s2) {
        cudaStreamCreateWithFlags(&s2, cudaStreamNonBlocking);
        cudaEventCreateWithFlags(&evF1, cudaEventDisableTiming);
        cudaEventCreateWithFlags(&evJ1, cudaEventDisableTiming);
        cudaEventCreateWithFlags(&evF2, cudaEventDisableTiming);
        cudaEventCreateWithFlags(&evJ2, cudaEventDisableTiming);
        cudaEventCreateWithFlags(&evF3, cudaEventDisableTiming);
        cudaEventCreateWithFlags(&evJ3, cudaEventDisableTiming);
    }

    // ---- fork 1: splits on s2, router chain on main ----
    cudaEventRecord(evF1, 0);
    cudaStreamWaitEvent(s2, evF1, 0);
    k_splitxip<<<16384, 256, 0, s2>>>(x, IP);

    k_gcmax<<<dim3(16, 16), 256>>>(x);
    k_mlp_logits<<<dim3(16, BB), 256>>>(W1, b1, lng, lnb, W2, b2, NK);
    k_selrank<<<dim3(NIN / 256, 8, BB), 256>>>((const float*)p_logits, NIN, (int*)p_rank);
    k_compact<<<BB, 1024>>>((const int*)p_rank, NIN, KIN, (int*)p_iidx2);

    cudaEventRecord(evJ1, s2);
    cudaStreamWaitEvent(0, evJ1, 0);

    // ---- fork 2: gatherW on s2 overlapping sel GEMM on main ----
    cudaEventRecord(evF2, 0);
    cudaStreamWaitEvent(s2, evF2, 0);
    k_gatherW<<<dim3(KIN / 512, NPROC / 32, BB), 512, 0, s2>>>(PW);

    k_gemm_h<3, 1, 1, 1><<<dim3(KIN / 128, SS / 128, BB), 512, SM3>>>(
        (const __half*)p_xh, (const __half*)p_xl, (const __half*)p_iph, (const __half*)p_ipl,
        (const int*)p_iidx2, KIN, p_selh, p_sell, DD, KIN,
        (size_t)SS * DD, 0, (size_t)SS * KIN);

    cudaEventRecord(evJ2, s2);
    cudaStreamWaitEvent(0, evJ2, 0);

    // ---- proc GEMM -> fp16 proc + score partials ----
    k_gemm_h<3, 1, 2, 0><<<dim3(NPROC / 128, SS / 128, BB), 512, SM3>>>(
        (const __half*)p_selh, (const __half*)p_sell, (const __half*)p_wgh, (const __half*)p_wgl,
        nullptr, 0, p_proch, nullptr, KIN, NPROC,
        (size_t)SS * KIN, (size_t)NPROC * KIN, (size_t)SS * NPROC);

    // ---- process selection ----
    k_scores2<<<dim3(NPROC / 256, BB), 256>>>();
    k_selrank<<<dim3(NPROC / 256, 8, BB), 256>>>((const float*)p_scores, NPROC, (int*)p_rank);
    k_compact<<<BB, 1024>>>((const int*)p_rank, NPROC, KPROC, (int*)p_pidx2);

    // ---- fork 3: batch-pipelined gathers + out GEMM ----
    cudaEventRecord(evF3, 0);
    cudaStreamWaitEvent(s2, evF3, 0);
    k_gsp_pot<<<32768 + 4096, 256, 0, s2>>>(PO, 2);   // batches 2-3 on side stream

    k_gsp_pot<<<32768 + 4096, 256>>>(PO, 0);          // batches 0-1 on main
    k_gemm_h<1, 0, 0, 0><<<dim3(DD / 128, SS / 128, 2), 512, SM1>>>(
        (const __half*)p_sph, (const __half*)p_sph, (const __half*)p_poth, (const __half*)p_poth,
        nullptr, 0, out, nullptr, KPROC, DD,
        (size_t)SS * KPROC, (size_t)DD * KPROC, (size_t)SS * DD);

    cudaEventRecord(evJ3, s2);
    cudaStreamWaitEvent(0, evJ3, 0);

    k_gemm_h<1, 0, 0, 0><<<dim3(DD / 128, SS / 128, 2), 512, SM1>>>(
        (const __half*)p_sph + (size_t)2 * SS * KPROC, (const __half*)p_sph,
        (const __half*)p_poth + (size_t)2 * DD * KPROC, (const __half*)p_poth,
        nullptr, 0, out + (size_t)2 * SS * DD, nullptr, KPROC, DD,
        (size_t)SS * KPROC, (size_t)DD * KPROC, (size_t)SS * DD);
}